// round 4
// baseline (speedup 1.0000x reference)
#include <cuda_runtime.h>

// CircularNN R3: lane = sample (32 samples/CTA), 1024 threads = 32 warps, 1 CTA/SM.
// Gather banks = lane*17 + j (j warp-uniform) -> permutation of 32 banks: conflict-free.
// Weight/idx loads are warp-uniform (1 wavefront). Custom erf (A&S 7.1.26, |err|<1.5e-7).

#define D     784
#define PAD   785
#define S     32      // samples per block (= lanes)
#define NW    32      // warps per block
#define NT    1024
#define NCLS  10

__device__ __forceinline__ float gelu_fast(float x) {
    // gelu(x) = 0.5 x (1 + erf(x/sqrt(2))), erf via Abramowitz-Stegun 7.1.26
    float u  = 0.70710678118654752f * x;
    float au = fabsf(u);
    float t  = __fdividef(1.0f, fmaf(0.3275911f, au, 1.0f));
    float e  = __expf(-u * u);
    float p  = fmaf(t, 1.061405429f, -1.453152027f);
    p = fmaf(t, p, 1.421413741f);
    p = fmaf(t, p, -0.284496736f);
    p = fmaf(t, p, 0.254829592f);
    p = p * t;
    float erfa = fmaf(-p, e, 1.0f);        // erf(|u|)
    float erfv = copysignf(erfa, u);       // erf(u)
    return 0.5f * x * (1.0f + erfv);
}

template<int K>
__device__ __forceinline__ void sparse_layer_f(
    const float* __restrict__ src, float* __restrict__ dst,
    const int* __restrict__ idx, const float* __restrict__ w,
    const float* __restrict__ bias, int lane, int warp)
{
    const float* srow = src + lane * PAD;
    float*       drow = dst + lane * PAD;
    #pragma unroll 2
    for (int f = warp; f < D; f += NW) {
        float acc = __ldg(bias + f);
        if constexpr (K == 2) {
            int2   j  = __ldg((const int2*)(idx) + f);
            float2 ww = __ldg((const float2*)(w) + f);
            acc = fmaf(ww.x, srow[j.x], acc);
            acc = fmaf(ww.y, srow[j.y], acc);
        } else if constexpr (K == 4) {
            int4   j  = __ldg((const int4*)(idx) + f);
            float4 ww = __ldg((const float4*)(w) + f);
            float t  = ww.y * srow[j.y];
            acc = fmaf(ww.x, srow[j.x], acc);
            t   = fmaf(ww.w, srow[j.w], t);
            acc = fmaf(ww.z, srow[j.z], acc);
            acc += t;
        } else {  // K == 8, two accumulation trees
            int4   ja = __ldg((const int4*)(idx) + 2 * f);
            int4   jb = __ldg((const int4*)(idx) + 2 * f + 1);
            float4 wa = __ldg((const float4*)(w) + 2 * f);
            float4 wb = __ldg((const float4*)(w) + 2 * f + 1);
            float t = wa.y * srow[ja.y];
            acc = fmaf(wa.x, srow[ja.x], acc);
            t   = fmaf(wa.w, srow[ja.w], t);
            acc = fmaf(wa.z, srow[ja.z], acc);
            t   = fmaf(wb.y, srow[jb.y], t);
            acc = fmaf(wb.x, srow[jb.x], acc);
            t   = fmaf(wb.w, srow[jb.w], t);
            acc = fmaf(wb.z, srow[jb.z], acc);
            acc += t;
        }
        drow[f] = gelu_fast(acc);
    }
}

extern __shared__ float smem[];

__global__ __launch_bounds__(NT, 1)
void circnn_kernel(const float* __restrict__ x,
                   const int*   __restrict__ idx1, const float* __restrict__ w1, const float* __restrict__ b1,
                   const int*   __restrict__ idx2, const float* __restrict__ w2, const float* __restrict__ b2,
                   const int*   __restrict__ idx3, const float* __restrict__ w3, const float* __restrict__ b3,
                   const float* __restrict__ fc_w, const float* __restrict__ fc_b,
                   float* __restrict__ out, int B)
{
    float* bufA = smem;                 // S*PAD floats
    float* bufB = smem + S * PAD;       // S*PAD floats
    float* part = smem;                 // alias bufA (dead after layer3): NW*S*NCLS = 10240 floats
    float* lgts = smem + NW * S * NCLS; // alias bufA tail: S*NCLS = 320 floats

    const int tid  = threadIdx.x;
    const int lane = tid & 31;
    const int warp = tid >> 5;
    const long base = (long)blockIdx.x * S;

    // --- load 32 sample rows of x (float4, coalesced) ---
    {
        const float4* x4 = (const float4*)(x + base * (long)D);
        for (int i = tid; i < S * (D / 4); i += NT) {
            int s0 = i / (D / 4);
            int d4 = i - s0 * (D / 4);
            float4 v;
            if (base + s0 < B) v = __ldg(x4 + i);
            else               v = make_float4(0.f, 0.f, 0.f, 0.f);
            float* p = bufA + s0 * PAD + d4 * 4;
            p[0] = v.x; p[1] = v.y; p[2] = v.z; p[3] = v.w;
        }
    }
    __syncthreads();

    sparse_layer_f<2>(bufA, bufB, idx1, w1, b1, lane, warp);
    __syncthreads();
    sparse_layer_f<4>(bufB, bufA, idx2, w2, b2, lane, warp);
    __syncthreads();
    sparse_layer_f<8>(bufA, bufB, idx3, w3, b3, lane, warp);
    __syncthreads();

    // --- FC partials: lane = sample, warp owns strided float4 feature chunks ---
    {
        float acc[NCLS];
        #pragma unroll
        for (int c = 0; c < NCLS; ++c) acc[c] = 0.0f;

        const float* hrow = bufB + lane * PAD;
        for (int c4 = warp; c4 < D / 4; c4 += NW) {
            const int f = c4 * 4;
            float h0 = hrow[f + 0];
            float h1 = hrow[f + 1];
            float h2 = hrow[f + 2];
            float h3 = hrow[f + 3];
            #pragma unroll
            for (int c = 0; c < NCLS; ++c) {
                float4 wv = __ldg((const float4*)(fc_w + c * D) + c4);
                acc[c] = fmaf(h0, wv.x,
                         fmaf(h1, wv.y,
                         fmaf(h2, wv.z,
                         fmaf(h3, wv.w, acc[c]))));
            }
        }
        __syncthreads();   // bufA fully dead before aliasing as `part`
        float* p = part + (warp * S + lane) * NCLS;
        #pragma unroll
        for (int c = 0; c < NCLS; ++c) p[c] = acc[c];
    }
    __syncthreads();

    // --- stage 1 reduction: 320 threads, one (sample, class) each ---
    if (tid < S * NCLS) {
        const int s = tid / NCLS;
        const int c = tid - s * NCLS;
        float sum = __ldg(fc_b + c);
        #pragma unroll 8
        for (int w = 0; w < NW; ++w)
            sum += part[(w * S + s) * NCLS + c];
        lgts[s * NCLS + c] = sum;
    }
    __syncthreads();

    // --- softmax: thread t handles sample t ---
    if (tid < S) {
        const long gs = base + tid;
        if (gs < B) {
            float l[NCLS];
            #pragma unroll
            for (int c = 0; c < NCLS; ++c) l[c] = lgts[tid * NCLS + c];
            float m = l[0];
            #pragma unroll
            for (int c = 1; c < NCLS; ++c) m = fmaxf(m, l[c]);
            float sum = 0.0f;
            #pragma unroll
            for (int c = 0; c < NCLS; ++c) { l[c] = __expf(l[c] - m); sum += l[c]; }
            const float inv = __fdividef(1.0f, sum);
            float* o = out + gs * NCLS;
            #pragma unroll
            for (int c = 0; c < NCLS; ++c) o[c] = l[c] * inv;
        }
    }
}

extern "C" void kernel_launch(void* const* d_in, const int* in_sizes, int n_in,
                              void* d_out, int out_size)
{
    const float* x    = (const float*)d_in[0];
    const int*   idx1 = (const int*)  d_in[1];
    const float* w1   = (const float*)d_in[2];
    const float* b1   = (const float*)d_in[3];
    const int*   idx2 = (const int*)  d_in[4];
    const float* w2   = (const float*)d_in[5];
    const float* b2   = (const float*)d_in[6];
    const int*   idx3 = (const int*)  d_in[7];
    const float* w3   = (const float*)d_in[8];
    const float* b3   = (const float*)d_in[9];
    const float* fc_w = (const float*)d_in[10];
    const float* fc_b = (const float*)d_in[11];
    float* out = (float*)d_out;

    const int B = in_sizes[0] / D;
    const int grid = (B + S - 1) / S;
    const int smem_bytes = 2 * S * PAD * (int)sizeof(float);  // 200,960

    cudaFuncSetAttribute(circnn_kernel,
                         cudaFuncAttributeMaxDynamicSharedMemorySize, smem_bytes);

    circnn_kernel<<<grid, NT, smem_bytes>>>(x, idx1, w1, b1, idx2, w2, b2,
                                            idx3, w3, b3, fc_w, fc_b, out, B);
}

// round 5
// speedup vs baseline: 1.7031x; 1.7031x over previous
#include <cuda_runtime.h>
#include <cuda_fp16.h>

// CircularNN R4: S=32 samples/CTA (lane = sample), NT=512 (16 warps), fp16
// activation ping-pong in SMEM (~100.6KB) -> 2 CTAs/SM = 32 warps/SM.
// Gathers: 1 LDS.U16 per (feature,tap) serves 32 samples, bank = 9s + (j>>1)
// mod 32 (bijection) -> conflict-free. Weights/idx warp-uniform LDG.
// All arithmetic fp32; only intermediate activations stored fp16.

#define D      784
#define PAD16  786     // even, 786*2/4 = 393 words, 393 mod 32 = 9 (odd) -> conflict-free
#define S      32      // samples per block (= lanes)
#define NW     16      // warps per block
#define NT     512
#define NCLS   10
#define NPW    49      // features per warp per layer

__device__ __forceinline__ float gelu_fast(float x) {
    // gelu(x) = 0.5 x (1 + erf(x/sqrt(2))), erf via Abramowitz-Stegun 7.1.26
    float u  = 0.70710678118654752f * x;
    float au = fabsf(u);
    float t  = __fdividef(1.0f, fmaf(0.3275911f, au, 1.0f));
    float e  = __expf(-u * u);
    float p  = fmaf(t, 1.061405429f, -1.453152027f);
    p = fmaf(t, p, 1.421413741f);
    p = fmaf(t, p, -0.284496736f);
    p = fmaf(t, p, 0.254829592f);
    p = p * t;
    float erfa = fmaf(-p, e, 1.0f);
    float erfv = copysignf(erfa, u);
    return 0.5f * x * (1.0f + erfv);
}

template<int K>
__device__ __forceinline__ void sparse_layer_h(
    const __half* __restrict__ src, __half* __restrict__ dst,
    const int* __restrict__ idx, const float* __restrict__ w,
    const float* __restrict__ bias, int lane, int warp)
{
    const __half* srow = src + lane * PAD16;
    __half*       drow = dst + lane * PAD16;
    const int n0 = warp * NPW;
    #pragma unroll 1
    for (int f = n0; f < n0 + NPW; ++f) {
        float acc = __ldg(bias + f);
        if constexpr (K == 2) {
            int2   j  = __ldg((const int2*)(idx) + f);
            float2 ww = __ldg((const float2*)(w) + f);
            acc = fmaf(ww.x, __half2float(srow[j.x]), acc);
            acc = fmaf(ww.y, __half2float(srow[j.y]), acc);
        } else if constexpr (K == 4) {
            int4   j  = __ldg((const int4*)(idx) + f);
            float4 ww = __ldg((const float4*)(w) + f);
            float t  = ww.y * __half2float(srow[j.y]);
            acc = fmaf(ww.x, __half2float(srow[j.x]), acc);
            t   = fmaf(ww.w, __half2float(srow[j.w]), t);
            acc = fmaf(ww.z, __half2float(srow[j.z]), acc);
            acc += t;
        } else {  // K == 8, two accumulation trees
            int4   ja = __ldg((const int4*)(idx) + 2 * f);
            int4   jb = __ldg((const int4*)(idx) + 2 * f + 1);
            float4 wa = __ldg((const float4*)(w) + 2 * f);
            float4 wb = __ldg((const float4*)(w) + 2 * f + 1);
            float t = wa.y * __half2float(srow[ja.y]);
            acc = fmaf(wa.x, __half2float(srow[ja.x]), acc);
            t   = fmaf(wa.w, __half2float(srow[ja.w]), t);
            acc = fmaf(wa.z, __half2float(srow[ja.z]), acc);
            t   = fmaf(wb.y, __half2float(srow[jb.y]), t);
            acc = fmaf(wb.x, __half2float(srow[jb.x]), acc);
            t   = fmaf(wb.w, __half2float(srow[jb.w]), t);
            acc = fmaf(wb.z, __half2float(srow[jb.z]), acc);
            acc += t;
        }
        drow[f] = __float2half_rn(gelu_fast(acc));
    }
}

extern __shared__ __align__(16) char smem_raw[];

__global__ __launch_bounds__(NT, 2)
void circnn_kernel(const float* __restrict__ x,
                   const int*   __restrict__ idx1, const float* __restrict__ w1, const float* __restrict__ b1,
                   const int*   __restrict__ idx2, const float* __restrict__ w2, const float* __restrict__ b2,
                   const int*   __restrict__ idx3, const float* __restrict__ w3, const float* __restrict__ b3,
                   const float* __restrict__ fc_w, const float* __restrict__ fc_b,
                   float* __restrict__ out, int B)
{
    __half* bufA = (__half*)smem_raw;            // S*PAD16 halves (50,304 B)
    __half* bufB = bufA + S * PAD16;             // S*PAD16 halves
    float*  part = (float*)smem_raw;             // alias bufA (dead after layer3): NW*S*NCLS floats = 20,480 B
    float*  lgts = part + NW * S * NCLS;         // S*NCLS floats = 1,280 B (fits in bufA region)

    const int tid  = threadIdx.x;
    const int lane = tid & 31;
    const int warp = tid >> 5;
    const long base = (long)blockIdx.x * S;

    // --- load 32 sample rows of x (float4, coalesced), convert to fp16 ---
    {
        const float4* x4 = (const float4*)(x + base * (long)D);
        for (int i = tid; i < S * (D / 4); i += NT) {
            int s0 = i / (D / 4);
            int d4 = i - s0 * (D / 4);
            float4 v;
            if (base + s0 < B) v = __ldg(x4 + i);
            else               v = make_float4(0.f, 0.f, 0.f, 0.f);
            __half2* hp = (__half2*)(bufA + s0 * PAD16 + d4 * 4);
            hp[0] = __floats2half2_rn(v.x, v.y);
            hp[1] = __floats2half2_rn(v.z, v.w);
        }
    }
    __syncthreads();

    sparse_layer_h<2>(bufA, bufB, idx1, w1, b1, lane, warp);
    __syncthreads();
    sparse_layer_h<4>(bufB, bufA, idx2, w2, b2, lane, warp);
    __syncthreads();
    sparse_layer_h<8>(bufA, bufB, idx3, w3, b3, lane, warp);
    __syncthreads();

    // --- FC partials: lane = sample, warp owns strided float4 feature chunks ---
    {
        float acc[NCLS];
        #pragma unroll
        for (int c = 0; c < NCLS; ++c) acc[c] = 0.0f;

        const __half2* hrow2 = (const __half2*)(bufB + lane * PAD16);
        for (int c4 = warp; c4 < D / 4; c4 += NW) {
            float2 ha = __half22float2(hrow2[c4 * 2 + 0]);
            float2 hb = __half22float2(hrow2[c4 * 2 + 1]);
            #pragma unroll
            for (int c = 0; c < NCLS; ++c) {
                float4 wv = __ldg((const float4*)(fc_w + c * D) + c4);
                acc[c] = fmaf(ha.x, wv.x,
                         fmaf(ha.y, wv.y,
                         fmaf(hb.x, wv.z,
                         fmaf(hb.y, wv.w, acc[c]))));
            }
        }
        __syncthreads();   // everyone done reading bufB; bufA dead -> alias as part
        float* p = part + (warp * S + lane) * NCLS;
        #pragma unroll
        for (int c = 0; c < NCLS; ++c) p[c] = acc[c];
    }
    __syncthreads();

    // --- stage 1 reduction: 320 threads, one (sample, class) each ---
    if (tid < S * NCLS) {
        const int s = tid / NCLS;
        const int c = tid - s * NCLS;
        float sum = __ldg(fc_b + c);
        #pragma unroll
        for (int w = 0; w < NW; ++w)
            sum += part[(w * S + s) * NCLS + c];
        lgts[s * NCLS + c] = sum;
    }
    __syncthreads();

    // --- softmax: thread t handles sample t ---
    if (tid < S) {
        const long gs = base + tid;
        if (gs < B) {
            float l[NCLS];
            #pragma unroll
            for (int c = 0; c < NCLS; ++c) l[c] = lgts[tid * NCLS + c];
            float m = l[0];
            #pragma unroll
            for (int c = 1; c < NCLS; ++c) m = fmaxf(m, l[c]);
            float sum = 0.0f;
            #pragma unroll
            for (int c = 0; c < NCLS; ++c) { l[c] = __expf(l[c] - m); sum += l[c]; }
            const float inv = __fdividef(1.0f, sum);
            float* o = out + gs * NCLS;
            #pragma unroll
            for (int c = 0; c < NCLS; ++c) o[c] = l[c] * inv;
        }
    }
}

extern "C" void kernel_launch(void* const* d_in, const int* in_sizes, int n_in,
                              void* d_out, int out_size)
{
    const float* x    = (const float*)d_in[0];
    const int*   idx1 = (const int*)  d_in[1];
    const float* w1   = (const float*)d_in[2];
    const float* b1   = (const float*)d_in[3];
    const int*   idx2 = (const int*)  d_in[4];
    const float* w2   = (const float*)d_in[5];
    const float* b2   = (const float*)d_in[6];
    const int*   idx3 = (const int*)  d_in[7];
    const float* w3   = (const float*)d_in[8];
    const float* b3   = (const float*)d_in[9];
    const float* fc_w = (const float*)d_in[10];
    const float* fc_b = (const float*)d_in[11];
    float* out = (float*)d_out;

    const int B = in_sizes[0] / D;
    const int grid = (B + S - 1) / S;
    const int smem_bytes = 2 * S * PAD16 * (int)sizeof(__half);  // 100,608

    cudaFuncSetAttribute(circnn_kernel,
                         cudaFuncAttributeMaxDynamicSharedMemorySize, smem_bytes);

    circnn_kernel<<<grid, NT, smem_bytes>>>(x, idx1, w1, b1, idx2, w2, b2,
                                            idx3, w3, b3, fc_w, fc_b, out, B);
}

// round 6
// speedup vs baseline: 2.1650x; 1.2712x over previous
#include <cuda_runtime.h>
#include <cuda_fp16.h>

// CircularNN R5: sample-pair interleaved fp16 activations.
// buf[(p, f)] = half2{sample 2p, sample 2p+1} of feature f.
// Lane = {fo:1, p:4}: warp covers 2 features x 32 samples per step.
// Gather: 1 LDS.32 serves 2 samples. idx/w/bias LDGs half-warp uniform
// (adjacent features -> same cache line). All math fp32; storage fp16.

#define D      784
#define PADH2  785    // half2 elements per pair-row (odd -> conflict-free p-stride)
#define S      32     // samples per block
#define NPAIR  16
#define NW     16     // warps per block
#define NT     512
#define NCLS   10
#define NFP    392    // feature pairs per layer

__device__ __forceinline__ float gelu_fast(float x) {
    // gelu(x) = 0.5 x (1 + erf(x/sqrt(2))), erf via Abramowitz-Stegun 7.1.26
    float u  = 0.70710678118654752f * x;
    float au = fabsf(u);
    float t  = __fdividef(1.0f, fmaf(0.3275911f, au, 1.0f));
    float e  = __expf(-u * u);
    float p  = fmaf(t, 1.061405429f, -1.453152027f);
    p = fmaf(t, p, 1.421413741f);
    p = fmaf(t, p, -0.284496736f);
    p = fmaf(t, p, 0.254829592f);
    p = p * t;
    float erfa = fmaf(-p, e, 1.0f);
    float erfv = copysignf(erfa, u);
    return 0.5f * x * (1.0f + erfv);
}

template<int K>
__device__ __forceinline__ void sparse_layer_p(
    const __half2* __restrict__ src, __half2* __restrict__ dst,
    const int* __restrict__ idx, const float* __restrict__ w,
    const float* __restrict__ bias, int p, int fo, int warp)
{
    const __half2* srow = src + p * PADH2;
    __half2*       drow = dst + p * PADH2;
    #pragma unroll 1
    for (int pb = warp; pb < NFP; pb += NW) {
        const int f = 2 * pb + fo;
        const float b = __ldg(bias + f);
        float ax = b, ay = b;
        if constexpr (K == 2) {
            int2   j  = __ldg((const int2*)(idx) + f);
            float2 ww = __ldg((const float2*)(w) + f);
            float2 g0 = __half22float2(srow[j.x]);
            float2 g1 = __half22float2(srow[j.y]);
            ax = fmaf(ww.x, g0.x, ax);  ay = fmaf(ww.x, g0.y, ay);
            ax = fmaf(ww.y, g1.x, ax);  ay = fmaf(ww.y, g1.y, ay);
        } else if constexpr (K == 4) {
            int4   j  = __ldg((const int4*)(idx) + f);
            float4 ww = __ldg((const float4*)(w) + f);
            float2 g0 = __half22float2(srow[j.x]);
            float2 g1 = __half22float2(srow[j.y]);
            float2 g2 = __half22float2(srow[j.z]);
            float2 g3 = __half22float2(srow[j.w]);
            float tx = ww.y * g1.x,            ty = ww.y * g1.y;
            ax = fmaf(ww.x, g0.x, ax);         ay = fmaf(ww.x, g0.y, ay);
            tx = fmaf(ww.w, g3.x, tx);         ty = fmaf(ww.w, g3.y, ty);
            ax = fmaf(ww.z, g2.x, ax);         ay = fmaf(ww.z, g2.y, ay);
            ax += tx;                          ay += ty;
        } else {  // K == 8, two accumulation trees per sample
            int4   ja = __ldg((const int4*)(idx) + 2 * f);
            int4   jb = __ldg((const int4*)(idx) + 2 * f + 1);
            float4 wa = __ldg((const float4*)(w) + 2 * f);
            float4 wb = __ldg((const float4*)(w) + 2 * f + 1);
            float2 g0 = __half22float2(srow[ja.x]);
            float2 g1 = __half22float2(srow[ja.y]);
            float2 g2 = __half22float2(srow[ja.z]);
            float2 g3 = __half22float2(srow[ja.w]);
            float tx = wa.y * g1.x,            ty = wa.y * g1.y;
            ax = fmaf(wa.x, g0.x, ax);         ay = fmaf(wa.x, g0.y, ay);
            tx = fmaf(wa.w, g3.x, tx);         ty = fmaf(wa.w, g3.y, ty);
            ax = fmaf(wa.z, g2.x, ax);         ay = fmaf(wa.z, g2.y, ay);
            float2 g4 = __half22float2(srow[jb.x]);
            float2 g5 = __half22float2(srow[jb.y]);
            float2 g6 = __half22float2(srow[jb.z]);
            float2 g7 = __half22float2(srow[jb.w]);
            tx = fmaf(wb.y, g5.x, tx);         ty = fmaf(wb.y, g5.y, ty);
            ax = fmaf(wb.x, g4.x, ax);         ay = fmaf(wb.x, g4.y, ay);
            tx = fmaf(wb.w, g7.x, tx);         ty = fmaf(wb.w, g7.y, ty);
            ax = fmaf(wb.z, g6.x, ax);         ay = fmaf(wb.z, g6.y, ay);
            ax += tx;                          ay += ty;
        }
        drow[f] = __floats2half2_rn(gelu_fast(ax), gelu_fast(ay));
    }
}

extern __shared__ __align__(16) char smem_raw[];

__global__ __launch_bounds__(NT, 2)
void circnn_kernel(const float* __restrict__ x,
                   const int*   __restrict__ idx1, const float* __restrict__ w1, const float* __restrict__ b1,
                   const int*   __restrict__ idx2, const float* __restrict__ w2, const float* __restrict__ b2,
                   const int*   __restrict__ idx3, const float* __restrict__ w3, const float* __restrict__ b3,
                   const float* __restrict__ fc_w, const float* __restrict__ fc_b,
                   float* __restrict__ out, int B)
{
    __half2* bufA = (__half2*)smem_raw;          // NPAIR*PADH2 half2 = 50,240 B
    __half2* bufB = bufA + NPAIR * PADH2;        // same size
    float*   part = (float*)smem_raw;            // alias bufA after layer3: NW*S*NCLS floats
    float*   lgts = part + NW * S * NCLS;        // S*NCLS floats

    const int tid  = threadIdx.x;
    const int lane = tid & 31;
    const int warp = tid >> 5;
    const int p    = lane & 15;   // sample pair
    const int fo   = lane >> 4;   // feature offset within pair
    const long base = (long)blockIdx.x * S;

    // --- load 32 sample rows of x (float4), scatter into pair-interleaved fp16 ---
    {
        const float4* x4 = (const float4*)(x + base * (long)D);
        __half* hA = (__half*)bufA;
        for (int i = tid; i < S * (D / 4); i += NT) {
            int s0 = i / (D / 4);
            int d4 = i - s0 * (D / 4);
            float4 v;
            if (base + s0 < B) v = __ldg(x4 + i);
            else               v = make_float4(0.f, 0.f, 0.f, 0.f);
            const int pp = s0 >> 1, hi = s0 & 1;
            const int f  = d4 * 4;
            __half* hp = hA + (pp * PADH2 + f) * 2 + hi;
            hp[0] = __float2half_rn(v.x);
            hp[2] = __float2half_rn(v.y);
            hp[4] = __float2half_rn(v.z);
            hp[6] = __float2half_rn(v.w);
        }
    }
    __syncthreads();

    sparse_layer_p<2>(bufA, bufB, idx1, w1, b1, p, fo, warp);
    __syncthreads();
    sparse_layer_p<4>(bufB, bufA, idx2, w2, b2, p, fo, warp);
    __syncthreads();
    sparse_layer_p<8>(bufA, bufB, idx3, w3, b3, p, fo, warp);
    __syncthreads();

    // --- FC partials: lane = sample, warp strides 4-feature chunks ---
    {
        float acc[NCLS];
        #pragma unroll
        for (int c = 0; c < NCLS; ++c) acc[c] = 0.0f;

        const __half* hB = (const __half*)bufB;
        const int sp = lane >> 1, hi = lane & 1;
        const __half* hrow = hB + sp * (PADH2 * 2) + hi;
        for (int c4 = warp; c4 < D / 4; c4 += NW) {
            const int f = c4 * 4;
            float h0 = __half2float(hrow[(f + 0) * 2]);
            float h1 = __half2float(hrow[(f + 1) * 2]);
            float h2 = __half2float(hrow[(f + 2) * 2]);
            float h3 = __half2float(hrow[(f + 3) * 2]);
            #pragma unroll
            for (int c = 0; c < NCLS; ++c) {
                float4 wv = __ldg((const float4*)(fc_w + c * D) + c4);
                acc[c] = fmaf(h0, wv.x,
                         fmaf(h1, wv.y,
                         fmaf(h2, wv.z,
                         fmaf(h3, wv.w, acc[c]))));
            }
        }
        __syncthreads();   // bufA dead for everyone -> alias as part
        float* pp = part + (warp * S + lane) * NCLS;
        #pragma unroll
        for (int c = 0; c < NCLS; ++c) pp[c] = acc[c];
    }
    __syncthreads();

    // --- stage 1 reduction: 320 threads, one (sample, class) each ---
    if (tid < S * NCLS) {
        const int s = tid / NCLS;
        const int c = tid - s * NCLS;
        float sum = __ldg(fc_b + c);
        #pragma unroll
        for (int w = 0; w < NW; ++w)
            sum += part[(w * S + s) * NCLS + c];
        lgts[s * NCLS + c] = sum;
    }
    __syncthreads();

    // --- softmax: thread t handles sample t ---
    if (tid < S) {
        const long gs = base + tid;
        if (gs < B) {
            float l[NCLS];
            #pragma unroll
            for (int c = 0; c < NCLS; ++c) l[c] = lgts[tid * NCLS + c];
            float m = l[0];
            #pragma unroll
            for (int c = 1; c < NCLS; ++c) m = fmaxf(m, l[c]);
            float sum = 0.0f;
            #pragma unroll
            for (int c = 0; c < NCLS; ++c) { l[c] = __expf(l[c] - m); sum += l[c]; }
            const float inv = __fdividef(1.0f, sum);
            float* o = out + gs * NCLS;
            #pragma unroll
            for (int c = 0; c < NCLS; ++c) o[c] = l[c] * inv;
        }
    }
}

extern "C" void kernel_launch(void* const* d_in, const int* in_sizes, int n_in,
                              void* d_out, int out_size)
{
    const float* x    = (const float*)d_in[0];
    const int*   idx1 = (const int*)  d_in[1];
    const float* w1   = (const float*)d_in[2];
    const float* b1   = (const float*)d_in[3];
    const int*   idx2 = (const int*)  d_in[4];
    const float* w2   = (const float*)d_in[5];
    const float* b2   = (const float*)d_in[6];
    const int*   idx3 = (const int*)  d_in[7];
    const float* w3   = (const float*)d_in[8];
    const float* b3   = (const float*)d_in[9];
    const float* fc_w = (const float*)d_in[10];
    const float* fc_b = (const float*)d_in[11];
    float* out = (float*)d_out;

    const int B = in_sizes[0] / D;
    const int grid = (B + S - 1) / S;
    const int smem_bytes = 2 * NPAIR * PADH2 * (int)sizeof(__half2);  // 100,480

    cudaFuncSetAttribute(circnn_kernel,
                         cudaFuncAttributeMaxDynamicSharedMemorySize, smem_bytes);

    circnn_kernel<<<grid, NT, smem_bytes>>>(x, idx1, w1, b1, idx2, w2, b2,
                                            idx3, w3, b3, fc_w, fc_b, out, B);
}

// round 7
// speedup vs baseline: 2.2379x; 1.0337x over previous
#include <cuda_runtime.h>
#include <cuda_fp16.h>

// CircularNN R6: R5 layout (sample-pair interleaved fp16 activations,
// S=32, NT=512, 2 CTAs/SM) + packed f32x2 gelu (sm_103a FFMA2 via PTX)
// + unroll-2 on the light layers for LDS latency hiding.

#define D      784
#define PADH2  785
#define S      32
#define NPAIR  16
#define NW     16
#define NT     512
#define NCLS   10
#define NFP    392

typedef unsigned long long ull;

__device__ __forceinline__ ull pack2(float a, float b) {
    ull r; asm("mov.b64 %0, {%1, %2};" : "=l"(r) : "f"(a), "f"(b)); return r;
}
__device__ __forceinline__ void unpack2(ull v, float& a, float& b) {
    asm("mov.b64 {%0, %1}, %2;" : "=f"(a), "=f"(b) : "l"(v));
}
#define FMA2(d,a,b,c) asm("fma.rn.f32x2 %0, %1, %2, %3;" : "=l"(d) : "l"(a), "l"(b), "l"(c))
#define MUL2(d,a,b)   asm("mul.rn.f32x2 %0, %1, %2;"     : "=l"(d) : "l"(a), "l"(b))

// gelu on a packed sample pair. erf via A&S 7.1.26 (|err| <= 1.5e-7),
// all polynomial/scaling math in packed f32x2; RCP/EX2 scalar MUFU.
__device__ __forceinline__ __half2 gelu2(float ax, float ay) {
    const ull C_RS2  = pack2(0.70710678118654752f, 0.70710678118654752f);
    const ull C_A    = pack2(0.3275911f, 0.3275911f);
    const ull C_ONE  = pack2(1.0f, 1.0f);
    const ull C_NL2E = pack2(-1.4426950408889634f, -1.4426950408889634f);
    const ull C_HALF = pack2(0.5f, 0.5f);
    // negated A&S coefficients (so P = -p(t), erf = fma(P, e, 1))
    const ull C_N5 = pack2(-1.061405429f, -1.061405429f);
    const ull C_N4 = pack2( 1.453152027f,  1.453152027f);
    const ull C_N3 = pack2(-1.421413741f, -1.421413741f);
    const ull C_N2 = pack2( 0.284496736f,  0.284496736f);
    const ull C_N1 = pack2(-0.254829592f, -0.254829592f);

    ull X = pack2(ax, ay);
    ull U;  MUL2(U, X, C_RS2);                       // u = x / sqrt(2)
    ull AU = U & 0x7FFFFFFF7FFFFFFFULL;              // |u|
    ull T1; FMA2(T1, AU, C_A, C_ONE);                // 1 + a|u|
    float t1x, t1y; unpack2(T1, t1x, t1y);
    float tx, ty;
    asm("rcp.approx.f32 %0, %1;" : "=f"(tx) : "f"(t1x));
    asm("rcp.approx.f32 %0, %1;" : "=f"(ty) : "f"(t1y));
    ull U2; MUL2(U2, U, U);
    ull A2; MUL2(A2, U2, C_NL2E);                    // -u^2 * log2(e)
    float a2x, a2y; unpack2(A2, a2x, a2y);
    float ex, ey;
    asm("ex2.approx.f32 %0, %1;" : "=f"(ex) : "f"(a2x));
    asm("ex2.approx.f32 %0, %1;" : "=f"(ey) : "f"(a2y));
    ull T = pack2(tx, ty);
    ull E = pack2(ex, ey);
    ull P;  FMA2(P, T, C_N5, C_N4);
    FMA2(P, T, P, C_N3);
    FMA2(P, T, P, C_N2);
    FMA2(P, T, P, C_N1);
    MUL2(P, P, T);                                   // -p(t)
    ull R;  FMA2(R, P, E, C_ONE);                    // erf(|u|) = 1 - p e
    ull SGN = U & 0x8000000080000000ULL;
    ull ERF = R ^ SGN;                               // erf(u)
    ull XH; MUL2(XH, X, C_HALF);                     // x/2
    ull O;  FMA2(O, XH, ERF, XH);                    // 0.5 x (1 + erf)
    float ox, oy; unpack2(O, ox, oy);
    return __floats2half2_rn(ox, oy);
}

template<int K, int UNROLL>
__device__ __forceinline__ void sparse_layer_p(
    const __half2* __restrict__ src, __half2* __restrict__ dst,
    const int* __restrict__ idx, const float* __restrict__ w,
    const float* __restrict__ bias, int p, int fo, int warp)
{
    const __half2* srow = src + p * PADH2;
    __half2*       drow = dst + p * PADH2;
    #pragma unroll UNROLL
    for (int pb = warp; pb < NFP; pb += NW) {
        const int f = 2 * pb + fo;
        const float b = __ldg(bias + f);
        float ax = b, ay = b;
        if constexpr (K == 2) {
            int2   j  = __ldg((const int2*)(idx) + f);
            float2 ww = __ldg((const float2*)(w) + f);
            float2 g0 = __half22float2(srow[j.x]);
            float2 g1 = __half22float2(srow[j.y]);
            ax = fmaf(ww.x, g0.x, ax);  ay = fmaf(ww.x, g0.y, ay);
            ax = fmaf(ww.y, g1.x, ax);  ay = fmaf(ww.y, g1.y, ay);
        } else if constexpr (K == 4) {
            int4   j  = __ldg((const int4*)(idx) + f);
            float4 ww = __ldg((const float4*)(w) + f);
            float2 g0 = __half22float2(srow[j.x]);
            float2 g1 = __half22float2(srow[j.y]);
            float2 g2 = __half22float2(srow[j.z]);
            float2 g3 = __half22float2(srow[j.w]);
            float tx = ww.y * g1.x,            ty = ww.y * g1.y;
            ax = fmaf(ww.x, g0.x, ax);         ay = fmaf(ww.x, g0.y, ay);
            tx = fmaf(ww.w, g3.x, tx);         ty = fmaf(ww.w, g3.y, ty);
            ax = fmaf(ww.z, g2.x, ax);         ay = fmaf(ww.z, g2.y, ay);
            ax += tx;                          ay += ty;
        } else {  // K == 8
            int4   ja = __ldg((const int4*)(idx) + 2 * f);
            int4   jb = __ldg((const int4*)(idx) + 2 * f + 1);
            float4 wa = __ldg((const float4*)(w) + 2 * f);
            float4 wb = __ldg((const float4*)(w) + 2 * f + 1);
            float2 g0 = __half22float2(srow[ja.x]);
            float2 g1 = __half22float2(srow[ja.y]);
            float2 g2 = __half22float2(srow[ja.z]);
            float2 g3 = __half22float2(srow[ja.w]);
            float tx = wa.y * g1.x,            ty = wa.y * g1.y;
            ax = fmaf(wa.x, g0.x, ax);         ay = fmaf(wa.x, g0.y, ay);
            tx = fmaf(wa.w, g3.x, tx);         ty = fmaf(wa.w, g3.y, ty);
            ax = fmaf(wa.z, g2.x, ax);         ay = fmaf(wa.z, g2.y, ay);
            float2 g4 = __half22float2(srow[jb.x]);
            float2 g5 = __half22float2(srow[jb.y]);
            float2 g6 = __half22float2(srow[jb.z]);
            float2 g7 = __half22float2(srow[jb.w]);
            tx = fmaf(wb.y, g5.x, tx);         ty = fmaf(wb.y, g5.y, ty);
            ax = fmaf(wb.x, g4.x, ax);         ay = fmaf(wb.x, g4.y, ay);
            tx = fmaf(wb.w, g7.x, tx);         ty = fmaf(wb.w, g7.y, ty);
            ax = fmaf(wb.z, g6.x, ax);         ay = fmaf(wb.z, g6.y, ay);
            ax += tx;                          ay += ty;
        }
        drow[f] = gelu2(ax, ay);
    }
}

extern __shared__ __align__(16) char smem_raw[];

__global__ __launch_bounds__(NT, 2)
void circnn_kernel(const float* __restrict__ x,
                   const int*   __restrict__ idx1, const float* __restrict__ w1, const float* __restrict__ b1,
                   const int*   __restrict__ idx2, const float* __restrict__ w2, const float* __restrict__ b2,
                   const int*   __restrict__ idx3, const float* __restrict__ w3, const float* __restrict__ b3,
                   const float* __restrict__ fc_w, const float* __restrict__ fc_b,
                   float* __restrict__ out, int B)
{
    __half2* bufA = (__half2*)smem_raw;          // NPAIR*PADH2 half2 = 50,240 B
    __half2* bufB = bufA + NPAIR * PADH2;
    float*   part = (float*)smem_raw;            // alias bufA after layer3
    float*   lgts = part + NW * S * NCLS;

    const int tid  = threadIdx.x;
    const int lane = tid & 31;
    const int warp = tid >> 5;
    const int p    = lane & 15;
    const int fo   = lane >> 4;
    const long base = (long)blockIdx.x * S;

    // --- load 32 sample rows of x (float4), scatter into pair-interleaved fp16 ---
    {
        const float4* x4 = (const float4*)(x + base * (long)D);
        __half* hA = (__half*)bufA;
        for (int i = tid; i < S * (D / 4); i += NT) {
            int s0 = i / (D / 4);
            int d4 = i - s0 * (D / 4);
            float4 v;
            if (base + s0 < B) v = __ldg(x4 + i);
            else               v = make_float4(0.f, 0.f, 0.f, 0.f);
            const int pp = s0 >> 1, hi = s0 & 1;
            const int f  = d4 * 4;
            __half* hp = hA + (pp * PADH2 + f) * 2 + hi;
            hp[0] = __float2half_rn(v.x);
            hp[2] = __float2half_rn(v.y);
            hp[4] = __float2half_rn(v.z);
            hp[6] = __float2half_rn(v.w);
        }
    }
    __syncthreads();

    sparse_layer_p<2, 2>(bufA, bufB, idx1, w1, b1, p, fo, warp);
    __syncthreads();
    sparse_layer_p<4, 2>(bufB, bufA, idx2, w2, b2, p, fo, warp);
    __syncthreads();
    sparse_layer_p<8, 1>(bufA, bufB, idx3, w3, b3, p, fo, warp);
    __syncthreads();

    // --- FC partials: lane = sample, warp strides 4-feature chunks ---
    {
        float acc[NCLS];
        #pragma unroll
        for (int c = 0; c < NCLS; ++c) acc[c] = 0.0f;

        const __half* hB = (const __half*)bufB;
        const int sp = lane >> 1, hi = lane & 1;
        const __half* hrow = hB + sp * (PADH2 * 2) + hi;
        for (int c4 = warp; c4 < D / 4; c4 += NW) {
            const int f = c4 * 4;
            float h0 = __half2float(hrow[(f + 0) * 2]);
            float h1 = __half2float(hrow[(f + 1) * 2]);
            float h2 = __half2float(hrow[(f + 2) * 2]);
            float h3 = __half2float(hrow[(f + 3) * 2]);
            #pragma unroll
            for (int c = 0; c < NCLS; ++c) {
                float4 wv = __ldg((const float4*)(fc_w + c * D) + c4);
                acc[c] = fmaf(h0, wv.x,
                         fmaf(h1, wv.y,
                         fmaf(h2, wv.z,
                         fmaf(h3, wv.w, acc[c]))));
            }
        }
        __syncthreads();
        float* pp = part + (warp * S + lane) * NCLS;
        #pragma unroll
        for (int c = 0; c < NCLS; ++c) pp[c] = acc[c];
    }
    __syncthreads();

    // --- stage 1 reduction: 320 threads, one (sample, class) each ---
    if (tid < S * NCLS) {
        const int s = tid / NCLS;
        const int c = tid - s * NCLS;
        float sum = __ldg(fc_b + c);
        #pragma unroll
        for (int w = 0; w < NW; ++w)
            sum += part[(w * S + s) * NCLS + c];
        lgts[s * NCLS + c] = sum;
    }
    __syncthreads();

    // --- softmax: thread t handles sample t ---
    if (tid < S) {
        const long gs = base + tid;
        if (gs < B) {
            float l[NCLS];
            #pragma unroll
            for (int c = 0; c < NCLS; ++c) l[c] = lgts[tid * NCLS + c];
            float m = l[0];
            #pragma unroll
            for (int c = 1; c < NCLS; ++c) m = fmaxf(m, l[c]);
            float sum = 0.0f;
            #pragma unroll
            for (int c = 0; c < NCLS; ++c) { l[c] = __expf(l[c] - m); sum += l[c]; }
            const float inv = __fdividef(1.0f, sum);
            float* o = out + gs * NCLS;
            #pragma unroll
            for (int c = 0; c < NCLS; ++c) o[c] = l[c] * inv;
        }
    }
}

extern "C" void kernel_launch(void* const* d_in, const int* in_sizes, int n_in,
                              void* d_out, int out_size)
{
    const float* x    = (const float*)d_in[0];
    const int*   idx1 = (const int*)  d_in[1];
    const float* w1   = (const float*)d_in[2];
    const float* b1   = (const float*)d_in[3];
    const int*   idx2 = (const int*)  d_in[4];
    const float* w2   = (const float*)d_in[5];
    const float* b2   = (const float*)d_in[6];
    const int*   idx3 = (const int*)  d_in[7];
    const float* w3   = (const float*)d_in[8];
    const float* b3   = (const float*)d_in[9];
    const float* fc_w = (const float*)d_in[10];
    const float* fc_b = (const float*)d_in[11];
    float* out = (float*)d_out;

    const int B = in_sizes[0] / D;
    const int grid = (B + S - 1) / S;
    const int smem_bytes = 2 * NPAIR * PADH2 * (int)sizeof(__half2);  // 100,480

    cudaFuncSetAttribute(circnn_kernel,
                         cudaFuncAttributeMaxDynamicSharedMemorySize, smem_bytes);

    circnn_kernel<<<grid, NT, smem_bytes>>>(x, idx1, w1, b1, idx2, w2, b2,
                                            idx3, w3, b3, fc_w, fc_b, out, B);
}

// round 8
// speedup vs baseline: 2.4535x; 1.0963x over previous
#include <cuda_runtime.h>
#include <cuda_fp16.h>

// CircularNN R7: R6 + (a) PADH2=786 -> even-bank pair rows, 50% of gathers
// fully conflict-free, layer STS provably conflict-free; (b) warp-per-pair
// input stage with conflict-free STS.64; (c) FC feature-packed f32x2 FMA;
// (d) 3-term A&S erf.

#define D      784
#define PADH2  786    // 786 mod 32 = 18 -> pair banks all-even, parity splits fo groups
#define S      32
#define NPAIR  16
#define NW     16
#define NT     512
#define NCLS   10
#define NFP    392

typedef unsigned long long ull;

__device__ __forceinline__ ull pack2(float a, float b) {
    ull r; asm("mov.b64 %0, {%1, %2};" : "=l"(r) : "f"(a), "f"(b)); return r;
}
__device__ __forceinline__ void unpack2(ull v, float& a, float& b) {
    asm("mov.b64 {%0, %1}, %2;" : "=f"(a), "=f"(b) : "l"(v));
}
#define FMA2(d,a,b,c) asm("fma.rn.f32x2 %0, %1, %2, %3;" : "=l"(d) : "l"(a), "l"(b), "l"(c))
#define MUL2(d,a,b)   asm("mul.rn.f32x2 %0, %1, %2;"     : "=l"(d) : "l"(a), "l"(b))

// gelu on packed sample pair; erf via A&S 7.1.25 (3-term, |err| <= 2.5e-5).
__device__ __forceinline__ __half2 gelu2(float ax, float ay) {
    const ull C_RS2  = pack2(0.70710678118654752f, 0.70710678118654752f);
    const ull C_P    = pack2(0.47047f, 0.47047f);
    const ull C_ONE  = pack2(1.0f, 1.0f);
    const ull C_NL2E = pack2(-1.4426950408889634f, -1.4426950408889634f);
    const ull C_HALF = pack2(0.5f, 0.5f);
    // negated coefficients: P = -(a1 t + a2 t^2 + a3 t^3), erf = fma(P, e, 1)
    const ull C_N3 = pack2(-0.7478556f, -0.7478556f);
    const ull C_N2 = pack2( 0.0958798f,  0.0958798f);
    const ull C_N1 = pack2(-0.3480242f, -0.3480242f);

    ull X = pack2(ax, ay);
    ull U;  MUL2(U, X, C_RS2);                       // u = x / sqrt(2)
    ull AU = U & 0x7FFFFFFF7FFFFFFFULL;              // |u|
    ull T1; FMA2(T1, AU, C_P, C_ONE);                // 1 + p|u|
    float t1x, t1y; unpack2(T1, t1x, t1y);
    float tx, ty;
    asm("rcp.approx.f32 %0, %1;" : "=f"(tx) : "f"(t1x));
    asm("rcp.approx.f32 %0, %1;" : "=f"(ty) : "f"(t1y));
    ull U2; MUL2(U2, U, U);
    ull A2; MUL2(A2, U2, C_NL2E);                    // -u^2 * log2(e)
    float a2x, a2y; unpack2(A2, a2x, a2y);
    float ex, ey;
    asm("ex2.approx.f32 %0, %1;" : "=f"(ex) : "f"(a2x));
    asm("ex2.approx.f32 %0, %1;" : "=f"(ey) : "f"(a2y));
    ull T = pack2(tx, ty);
    ull E = pack2(ex, ey);
    ull P;  FMA2(P, T, C_N3, C_N2);
    FMA2(P, T, P, C_N1);
    MUL2(P, P, T);                                   // -(a1 t + a2 t^2 + a3 t^3)
    ull R;  FMA2(R, P, E, C_ONE);                    // erf(|u|)
    ull SGN = U & 0x8000000080000000ULL;
    ull ERF = R ^ SGN;                               // erf(u)
    ull XH; MUL2(XH, X, C_HALF);                     // x/2
    ull O;  FMA2(O, XH, ERF, XH);                    // 0.5 x (1 + erf)
    float ox, oy; unpack2(O, ox, oy);
    return __floats2half2_rn(ox, oy);
}

template<int K, int UNROLL>
__device__ __forceinline__ void sparse_layer_p(
    const __half2* __restrict__ src, __half2* __restrict__ dst,
    const int* __restrict__ idx, const float* __restrict__ w,
    const float* __restrict__ bias, int p, int fo, int warp)
{
    const __half2* srow = src + p * PADH2;
    __half2*       drow = dst + p * PADH2;
    #pragma unroll UNROLL
    for (int pb = warp; pb < NFP; pb += NW) {
        const int f = 2 * pb + fo;
        const float b = __ldg(bias + f);
        float ax = b, ay = b;
        if constexpr (K == 2) {
            int2   j  = __ldg((const int2*)(idx) + f);
            float2 ww = __ldg((const float2*)(w) + f);
            float2 g0 = __half22float2(srow[j.x]);
            float2 g1 = __half22float2(srow[j.y]);
            ax = fmaf(ww.x, g0.x, ax);  ay = fmaf(ww.x, g0.y, ay);
            ax = fmaf(ww.y, g1.x, ax);  ay = fmaf(ww.y, g1.y, ay);
        } else if constexpr (K == 4) {
            int4   j  = __ldg((const int4*)(idx) + f);
            float4 ww = __ldg((const float4*)(w) + f);
            float2 g0 = __half22float2(srow[j.x]);
            float2 g1 = __half22float2(srow[j.y]);
            float2 g2 = __half22float2(srow[j.z]);
            float2 g3 = __half22float2(srow[j.w]);
            float tx = ww.y * g1.x,            ty = ww.y * g1.y;
            ax = fmaf(ww.x, g0.x, ax);         ay = fmaf(ww.x, g0.y, ay);
            tx = fmaf(ww.w, g3.x, tx);         ty = fmaf(ww.w, g3.y, ty);
            ax = fmaf(ww.z, g2.x, ax);         ay = fmaf(ww.z, g2.y, ay);
            ax += tx;                          ay += ty;
        } else {  // K == 8
            int4   ja = __ldg((const int4*)(idx) + 2 * f);
            int4   jb = __ldg((const int4*)(idx) + 2 * f + 1);
            float4 wa = __ldg((const float4*)(w) + 2 * f);
            float4 wb = __ldg((const float4*)(w) + 2 * f + 1);
            float2 g0 = __half22float2(srow[ja.x]);
            float2 g1 = __half22float2(srow[ja.y]);
            float2 g2 = __half22float2(srow[ja.z]);
            float2 g3 = __half22float2(srow[ja.w]);
            float tx = wa.y * g1.x,            ty = wa.y * g1.y;
            ax = fmaf(wa.x, g0.x, ax);         ay = fmaf(wa.x, g0.y, ay);
            tx = fmaf(wa.w, g3.x, tx);         ty = fmaf(wa.w, g3.y, ty);
            ax = fmaf(wa.z, g2.x, ax);         ay = fmaf(wa.z, g2.y, ay);
            float2 g4 = __half22float2(srow[jb.x]);
            float2 g5 = __half22float2(srow[jb.y]);
            float2 g6 = __half22float2(srow[jb.z]);
            float2 g7 = __half22float2(srow[jb.w]);
            tx = fmaf(wb.y, g5.x, tx);         ty = fmaf(wb.y, g5.y, ty);
            ax = fmaf(wb.x, g4.x, ax);         ay = fmaf(wb.x, g4.y, ay);
            tx = fmaf(wb.w, g7.x, tx);         ty = fmaf(wb.w, g7.y, ty);
            ax = fmaf(wb.z, g6.x, ax);         ay = fmaf(wb.z, g6.y, ay);
            ax += tx;                          ay += ty;
        }
        drow[f] = gelu2(ax, ay);
    }
}

extern __shared__ __align__(16) char smem_raw[];

__global__ __launch_bounds__(NT, 2)
void circnn_kernel(const float* __restrict__ x,
                   const int*   __restrict__ idx1, const float* __restrict__ w1, const float* __restrict__ b1,
                   const int*   __restrict__ idx2, const float* __restrict__ w2, const float* __restrict__ b2,
                   const int*   __restrict__ idx3, const float* __restrict__ w3, const float* __restrict__ b3,
                   const float* __restrict__ fc_w, const float* __restrict__ fc_b,
                   float* __restrict__ out, int B)
{
    __half2* bufA = (__half2*)smem_raw;          // NPAIR*PADH2 half2 = 50,304 B
    __half2* bufB = bufA + NPAIR * PADH2;
    float*   part = (float*)smem_raw;            // alias bufA after layer3
    float*   lgts = part + NW * S * NCLS;

    const int tid  = threadIdx.x;
    const int lane = tid & 31;
    const int warp = tid >> 5;
    const int p    = lane & 15;
    const int fo   = lane >> 4;
    const long base = (long)blockIdx.x * S;

    // --- input: warp w owns sample pair w; coalesced row loads, conflict-free STS.64 ---
    {
        const long s0 = base + 2 * warp;
        const float4* r0 = (const float4*)(x + s0 * (long)D);
        const float4* r1 = (const float4*)(x + (s0 + 1) * (long)D);
        uint2* drow = (uint2*)((char*)smem_raw + (warp * PADH2) * 4);  // byte stride 3144, 8B aligned
        for (int k = lane; k < D / 4; k += 32) {
            float4 a = __ldg(r0 + k);
            float4 b = __ldg(r1 + k);
            __half2 h0 = __floats2half2_rn(a.x, b.x);
            __half2 h1 = __floats2half2_rn(a.y, b.y);
            __half2 h2 = __floats2half2_rn(a.z, b.z);
            __half2 h3 = __floats2half2_rn(a.w, b.w);
            uint2 v0, v1;
            v0.x = *(unsigned*)&h0;  v0.y = *(unsigned*)&h1;
            v1.x = *(unsigned*)&h2;  v1.y = *(unsigned*)&h3;
            drow[2 * k]     = v0;
            drow[2 * k + 1] = v1;
        }
    }
    __syncthreads();

    sparse_layer_p<2, 2>(bufA, bufB, idx1, w1, b1, p, fo, warp);
    __syncthreads();
    sparse_layer_p<4, 2>(bufB, bufA, idx2, w2, b2, p, fo, warp);
    __syncthreads();
    sparse_layer_p<8, 1>(bufA, bufB, idx3, w3, b3, p, fo, warp);
    __syncthreads();

    // --- FC partials: lane = sample; feature-packed f32x2 FMAs ---
    {
        ull acc2[NCLS];
        #pragma unroll
        for (int c = 0; c < NCLS; ++c) acc2[c] = pack2(0.0f, 0.0f);

        const __half* hB = (const __half*)bufB;
        const int sp = lane >> 1, hi = lane & 1;
        const __half* hrow = hB + sp * (PADH2 * 2) + hi;
        for (int c4 = warp; c4 < D / 4; c4 += NW) {
            const int f = c4 * 4;
            float h0 = __half2float(hrow[(f + 0) * 2]);
            float h1 = __half2float(hrow[(f + 1) * 2]);
            float h2 = __half2float(hrow[(f + 2) * 2]);
            float h3 = __half2float(hrow[(f + 3) * 2]);
            ull H01 = pack2(h0, h1);
            ull H23 = pack2(h2, h3);
            #pragma unroll
            for (int c = 0; c < NCLS; ++c) {
                float4 wv = __ldg((const float4*)(fc_w + c * D) + c4);
                ull W01 = pack2(wv.x, wv.y);   // register-pair from LDG.128 (mov coalesced)
                ull W23 = pack2(wv.z, wv.w);
                FMA2(acc2[c], W01, H01, acc2[c]);
                FMA2(acc2[c], W23, H23, acc2[c]);
            }
        }
        __syncthreads();   // bufA dead for everyone -> alias as part
        float* pp = part + (warp * S + lane) * NCLS;
        #pragma unroll
        for (int c = 0; c < NCLS; ++c) {
            float lo, hv; unpack2(acc2[c], lo, hv);
            pp[c] = lo + hv;
        }
    }
    __syncthreads();

    // --- stage 1 reduction: 320 threads, one (sample, class) each ---
    if (tid < S * NCLS) {
        const int s = tid / NCLS;
        const int c = tid - s * NCLS;
        float sum = __ldg(fc_b + c);
        #pragma unroll
        for (int w = 0; w < NW; ++w)
            sum += part[(w * S + s) * NCLS + c];
        lgts[s * NCLS + c] = sum;
    }
    __syncthreads();

    // --- softmax: thread t handles sample t ---
    if (tid < S) {
        const long gs = base + tid;
        if (gs < B) {
            float l[NCLS];
            #pragma unroll
            for (int c = 0; c < NCLS; ++c) l[c] = lgts[tid * NCLS + c];
            float m = l[0];
            #pragma unroll
            for (int c = 1; c < NCLS; ++c) m = fmaxf(m, l[c]);
            float sum = 0.0f;
            #pragma unroll
            for (int c = 0; c < NCLS; ++c) { l[c] = __expf(l[c] - m); sum += l[c]; }
            const float inv = __fdividef(1.0f, sum);
            float* o = out + gs * NCLS;
            #pragma unroll
            for (int c = 0; c < NCLS; ++c) o[c] = l[c] * inv;
        }
    }
}

extern "C" void kernel_launch(void* const* d_in, const int* in_sizes, int n_in,
                              void* d_out, int out_size)
{
    const float* x    = (const float*)d_in[0];
    const int*   idx1 = (const int*)  d_in[1];
    const float* w1   = (const float*)d_in[2];
    const float* b1   = (const float*)d_in[3];
    const int*   idx2 = (const int*)  d_in[4];
    const float* w2   = (const float*)d_in[5];
    const float* b2   = (const float*)d_in[6];
    const int*   idx3 = (const int*)  d_in[7];
    const float* w3   = (const float*)d_in[8];
    const float* b3   = (const float*)d_in[9];
    const float* fc_w = (const float*)d_in[10];
    const float* fc_b = (const float*)d_in[11];
    float* out = (float*)d_out;

    const int B = in_sizes[0] / D;
    const int grid = (B + S - 1) / S;
    const int smem_bytes = 2 * NPAIR * PADH2 * (int)sizeof(__half2);  // 100,608

    cudaFuncSetAttribute(circnn_kernel,
                         cudaFuncAttributeMaxDynamicSharedMemorySize, smem_bytes);

    circnn_kernel<<<grid, NT, smem_bytes>>>(x, idx1, w1, b1, idx2, w2, b2,
                                            idx3, w3, b3, fc_w, fc_b, out, B);
}

// round 9
// speedup vs baseline: 2.4919x; 1.0156x over previous
#include <cuda_runtime.h>
#include <cuda_fp16.h>

// CircularNN R8: R7 layout (sample-pair interleaved fp16 activations,
// S=32, NT=512, 2 CTAs/SM, PADH2=786) + sigmoid-form tanh-GELU in packed
// f32x2 (15 instr/pair vs 24 for A&S erf). gelu(x) ~= x * sigmoid(2z),
// 2z*log2e = x*(A + B x^2). Max abs deviation from exact erf-gelu ~4e-4.

#define D      784
#define PADH2  786
#define S      32
#define NPAIR  16
#define NW     16
#define NT     512
#define NCLS   10
#define NFP    392

typedef unsigned long long ull;

__device__ __forceinline__ ull pack2(float a, float b) {
    ull r; asm("mov.b64 %0, {%1, %2};" : "=l"(r) : "f"(a), "f"(b)); return r;
}
__device__ __forceinline__ void unpack2(ull v, float& a, float& b) {
    asm("mov.b64 {%0, %1}, %2;" : "=f"(a), "=f"(b) : "l"(v));
}
#define FMA2(d,a,b,c) asm("fma.rn.f32x2 %0, %1, %2, %3;" : "=l"(d) : "l"(a), "l"(b), "l"(c))
#define MUL2(d,a,b)   asm("mul.rn.f32x2 %0, %1, %2;"     : "=l"(d) : "l"(a), "l"(b))

// tanh-form gelu on a packed sample pair: x * sigma(2z), z = sqrt(2/pi)(x + 0.044715 x^3).
// 2z*log2e = x*(C_A + C_B x^2). sigma(2z) = e/(1+e), e = 2^(2z*log2e).
// Saturation-safe: e=inf -> R=0 -> out=x; e=0 -> R=1 -> out=0.
__device__ __forceinline__ __half2 gelu2(float ax, float ay) {
    const ull C_A    = pack2(2.30220764f, 2.30220764f);    // 2*log2(e)*sqrt(2/pi)
    const ull C_B    = pack2(0.10294321f, 0.10294321f);    // C_A * 0.044715
    const ull C_ONE  = pack2(1.0f, 1.0f);
    const ull C_NEG1 = pack2(-1.0f, -1.0f);

    ull X = pack2(ax, ay);
    ull T; MUL2(T, X, X);               // x^2
    ull V; FMA2(V, T, C_B, C_A);        // A + B x^2
    MUL2(V, V, X);                      // v = x(A + B x^2) = 2z*log2e
    float vx, vy; unpack2(V, vx, vy);
    float ex_, ey_;
    asm("ex2.approx.f32 %0, %1;" : "=f"(ex_) : "f"(vx));
    asm("ex2.approx.f32 %0, %1;" : "=f"(ey_) : "f"(vy));
    ull E = pack2(ex_, ey_);
    ull DEN; FMA2(DEN, E, C_ONE, C_ONE);  // 1 + e
    float dx, dy; unpack2(DEN, dx, dy);
    float rx, ry;
    asm("rcp.approx.f32 %0, %1;" : "=f"(rx) : "f"(dx));
    asm("rcp.approx.f32 %0, %1;" : "=f"(ry) : "f"(dy));
    ull R = pack2(rx, ry);
    ull N; MUL2(N, X, R);               // x / (1+e)
    ull O; FMA2(O, N, C_NEG1, X);       // x - x/(1+e) = x * e/(1+e)
    float ox, oy; unpack2(O, ox, oy);
    return __floats2half2_rn(ox, oy);
}

template<int K, int UNROLL>
__device__ __forceinline__ void sparse_layer_p(
    const __half2* __restrict__ src, __half2* __restrict__ dst,
    const int* __restrict__ idx, const float* __restrict__ w,
    const float* __restrict__ bias, int p, int fo, int warp)
{
    const __half2* srow = src + p * PADH2;
    __half2*       drow = dst + p * PADH2;
    #pragma unroll UNROLL
    for (int pb = warp; pb < NFP; pb += NW) {
        const int f = 2 * pb + fo;
        const float b = __ldg(bias + f);
        float ax = b, ay = b;
        if constexpr (K == 2) {
            int2   j  = __ldg((const int2*)(idx) + f);
            float2 ww = __ldg((const float2*)(w) + f);
            float2 g0 = __half22float2(srow[j.x]);
            float2 g1 = __half22float2(srow[j.y]);
            ax = fmaf(ww.x, g0.x, ax);  ay = fmaf(ww.x, g0.y, ay);
            ax = fmaf(ww.y, g1.x, ax);  ay = fmaf(ww.y, g1.y, ay);
        } else if constexpr (K == 4) {
            int4   j  = __ldg((const int4*)(idx) + f);
            float4 ww = __ldg((const float4*)(w) + f);
            float2 g0 = __half22float2(srow[j.x]);
            float2 g1 = __half22float2(srow[j.y]);
            float2 g2 = __half22float2(srow[j.z]);
            float2 g3 = __half22float2(srow[j.w]);
            float tx = ww.y * g1.x,            ty = ww.y * g1.y;
            ax = fmaf(ww.x, g0.x, ax);         ay = fmaf(ww.x, g0.y, ay);
            tx = fmaf(ww.w, g3.x, tx);         ty = fmaf(ww.w, g3.y, ty);
            ax = fmaf(ww.z, g2.x, ax);         ay = fmaf(ww.z, g2.y, ay);
            ax += tx;                          ay += ty;
        } else {  // K == 8
            int4   ja = __ldg((const int4*)(idx) + 2 * f);
            int4   jb = __ldg((const int4*)(idx) + 2 * f + 1);
            float4 wa = __ldg((const float4*)(w) + 2 * f);
            float4 wb = __ldg((const float4*)(w) + 2 * f + 1);
            float2 g0 = __half22float2(srow[ja.x]);
            float2 g1 = __half22float2(srow[ja.y]);
            float2 g2 = __half22float2(srow[ja.z]);
            float2 g3 = __half22float2(srow[ja.w]);
            float tx = wa.y * g1.x,            ty = wa.y * g1.y;
            ax = fmaf(wa.x, g0.x, ax);         ay = fmaf(wa.x, g0.y, ay);
            tx = fmaf(wa.w, g3.x, tx);         ty = fmaf(wa.w, g3.y, ty);
            ax = fmaf(wa.z, g2.x, ax);         ay = fmaf(wa.z, g2.y, ay);
            float2 g4 = __half22float2(srow[jb.x]);
            float2 g5 = __half22float2(srow[jb.y]);
            float2 g6 = __half22float2(srow[jb.z]);
            float2 g7 = __half22float2(srow[jb.w]);
            tx = fmaf(wb.y, g5.x, tx);         ty = fmaf(wb.y, g5.y, ty);
            ax = fmaf(wb.x, g4.x, ax);         ay = fmaf(wb.x, g4.y, ay);
            tx = fmaf(wb.w, g7.x, tx);         ty = fmaf(wb.w, g7.y, ty);
            ax = fmaf(wb.z, g6.x, ax);         ay = fmaf(wb.z, g6.y, ay);
            ax += tx;                          ay += ty;
        }
        drow[f] = gelu2(ax, ay);
    }
}

extern __shared__ __align__(16) char smem_raw[];

__global__ __launch_bounds__(NT, 2)
void circnn_kernel(const float* __restrict__ x,
                   const int*   __restrict__ idx1, const float* __restrict__ w1, const float* __restrict__ b1,
                   const int*   __restrict__ idx2, const float* __restrict__ w2, const float* __restrict__ b2,
                   const int*   __restrict__ idx3, const float* __restrict__ w3, const float* __restrict__ b3,
                   const float* __restrict__ fc_w, const float* __restrict__ fc_b,
                   float* __restrict__ out, int B)
{
    __half2* bufA = (__half2*)smem_raw;          // NPAIR*PADH2 half2 = 50,304 B
    __half2* bufB = bufA + NPAIR * PADH2;
    float*   part = (float*)smem_raw;            // alias bufA after layer3
    float*   lgts = part + NW * S * NCLS;

    const int tid  = threadIdx.x;
    const int lane = tid & 31;
    const int warp = tid >> 5;
    const int p    = lane & 15;
    const int fo   = lane >> 4;
    const long base = (long)blockIdx.x * S;

    // --- input: warp w owns sample pair w; coalesced row loads, conflict-free STS.64 ---
    {
        const long s0 = base + 2 * warp;
        const float4* r0 = (const float4*)(x + s0 * (long)D);
        const float4* r1 = (const float4*)(x + (s0 + 1) * (long)D);
        uint2* drow = (uint2*)((char*)smem_raw + (warp * PADH2) * 4);
        for (int k = lane; k < D / 4; k += 32) {
            float4 a = __ldg(r0 + k);
            float4 b = __ldg(r1 + k);
            __half2 h0 = __floats2half2_rn(a.x, b.x);
            __half2 h1 = __floats2half2_rn(a.y, b.y);
            __half2 h2 = __floats2half2_rn(a.z, b.z);
            __half2 h3 = __floats2half2_rn(a.w, b.w);
            uint2 v0, v1;
            v0.x = *(unsigned*)&h0;  v0.y = *(unsigned*)&h1;
            v1.x = *(unsigned*)&h2;  v1.y = *(unsigned*)&h3;
            drow[2 * k]     = v0;
            drow[2 * k + 1] = v1;
        }
    }
    __syncthreads();

    sparse_layer_p<2, 2>(bufA, bufB, idx1, w1, b1, p, fo, warp);
    __syncthreads();
    sparse_layer_p<4, 2>(bufB, bufA, idx2, w2, b2, p, fo, warp);
    __syncthreads();
    sparse_layer_p<8, 1>(bufA, bufB, idx3, w3, b3, p, fo, warp);
    __syncthreads();

    // --- FC partials: lane = sample; feature-packed f32x2 FMAs ---
    {
        ull acc2[NCLS];
        #pragma unroll
        for (int c = 0; c < NCLS; ++c) acc2[c] = pack2(0.0f, 0.0f);

        const __half* hB = (const __half*)bufB;
        const int sp = lane >> 1, hi = lane & 1;
        const __half* hrow = hB + sp * (PADH2 * 2) + hi;
        for (int c4 = warp; c4 < D / 4; c4 += NW) {
            const int f = c4 * 4;
            float h0 = __half2float(hrow[(f + 0) * 2]);
            float h1 = __half2float(hrow[(f + 1) * 2]);
            float h2 = __half2float(hrow[(f + 2) * 2]);
            float h3 = __half2float(hrow[(f + 3) * 2]);
            ull H01 = pack2(h0, h1);
            ull H23 = pack2(h2, h3);
            #pragma unroll
            for (int c = 0; c < NCLS; ++c) {
                float4 wv = __ldg((const float4*)(fc_w + c * D) + c4);
                ull W01 = pack2(wv.x, wv.y);
                ull W23 = pack2(wv.z, wv.w);
                FMA2(acc2[c], W01, H01, acc2[c]);
                FMA2(acc2[c], W23, H23, acc2[c]);
            }
        }
        __syncthreads();   // bufA dead for everyone -> alias as part
        float* pp = part + (warp * S + lane) * NCLS;
        #pragma unroll
        for (int c = 0; c < NCLS; ++c) {
            float lo, hv; unpack2(acc2[c], lo, hv);
            pp[c] = lo + hv;
        }
    }
    __syncthreads();

    // --- stage 1 reduction: 320 threads, one (sample, class) each ---
    if (tid < S * NCLS) {
        const int s = tid / NCLS;
        const int c = tid - s * NCLS;
        float sum = __ldg(fc_b + c);
        #pragma unroll
        for (int w = 0; w < NW; ++w)
            sum += part[(w * S + s) * NCLS + c];
        lgts[s * NCLS + c] = sum;
    }
    __syncthreads();

    // --- softmax: thread t handles sample t ---
    if (tid < S) {
        const long gs = base + tid;
        if (gs < B) {
            float l[NCLS];
            #pragma unroll
            for (int c = 0; c < NCLS; ++c) l[c] = lgts[tid * NCLS + c];
            float m = l[0];
            #pragma unroll
            for (int c = 1; c < NCLS; ++c) m = fmaxf(m, l[c]);
            float sum = 0.0f;
            #pragma unroll
            for (int c = 0; c < NCLS; ++c) { l[c] = __expf(l[c] - m); sum += l[c]; }
            const float inv = __fdividef(1.0f, sum);
            float* o = out + gs * NCLS;
            #pragma unroll
            for (int c = 0; c < NCLS; ++c) o[c] = l[c] * inv;
        }
    }
}

extern "C" void kernel_launch(void* const* d_in, const int* in_sizes, int n_in,
                              void* d_out, int out_size)
{
    const float* x    = (const float*)d_in[0];
    const int*   idx1 = (const int*)  d_in[1];
    const float* w1   = (const float*)d_in[2];
    const float* b1   = (const float*)d_in[3];
    const int*   idx2 = (const int*)  d_in[4];
    const float* w2   = (const float*)d_in[5];
    const float* b2   = (const float*)d_in[6];
    const int*   idx3 = (const int*)  d_in[7];
    const float* w3   = (const float*)d_in[8];
    const float* b3   = (const float*)d_in[9];
    const float* fc_w = (const float*)d_in[10];
    const float* fc_b = (const float*)d_in[11];
    float* out = (float*)d_out;

    const int B = in_sizes[0] / D;
    const int grid = (B + S - 1) / S;
    const int smem_bytes = 2 * NPAIR * PADH2 * (int)sizeof(__half2);  // 100,608

    cudaFuncSetAttribute(circnn_kernel,
                         cudaFuncAttributeMaxDynamicSharedMemorySize, smem_bytes);

    circnn_kernel<<<grid, NT, smem_bytes>>>(x, idx1, w1, b1, idx2, w2, b2,
                                            idx3, w3, b3, fc_w, fc_b, out, B);
}

// round 10
// speedup vs baseline: 2.6443x; 1.0612x over previous
#include <cuda_runtime.h>
#include <cuda_fp16.h>

// CircularNN R9: R8 layout (sample-pair interleaved fp16 activations,
// S=32, NT=512, 2 CTAs/SM, PADH2=786) + MUFU.TANH-based gelu (hardware
// tanh.approx.f32, ~11 instr/pair, short dependency chain) + unroll (4,4,1)
// on the sparse layers for LDS/LDG latency hiding.

#define D      784
#define PADH2  786
#define S      32
#define NPAIR  16
#define NW     16
#define NT     512
#define NCLS   10
#define NFP    392

typedef unsigned long long ull;

__device__ __forceinline__ ull pack2(float a, float b) {
    ull r; asm("mov.b64 %0, {%1, %2};" : "=l"(r) : "f"(a), "f"(b)); return r;
}
__device__ __forceinline__ void unpack2(ull v, float& a, float& b) {
    asm("mov.b64 {%0, %1}, %2;" : "=f"(a), "=f"(b) : "l"(v));
}
#define FMA2(d,a,b,c) asm("fma.rn.f32x2 %0, %1, %2, %3;" : "=l"(d) : "l"(a), "l"(b), "l"(c))
#define MUL2(d,a,b)   asm("mul.rn.f32x2 %0, %1, %2;"     : "=l"(d) : "l"(a), "l"(b))

// tanh-form gelu on a packed sample pair using hardware MUFU.TANH:
// gelu(x) = 0.5 x (1 + tanh(z)), z = sqrt(2/pi) (x + 0.044715 x^3) = x(A + B x^2).
__device__ __forceinline__ __half2 gelu2(float ax, float ay) {
    const ull C_A    = pack2(0.7978845608f, 0.7978845608f);
    const ull C_B    = pack2(0.0356774081f, 0.0356774081f);
    const ull C_HALF = pack2(0.5f, 0.5f);

    ull X = pack2(ax, ay);
    ull T; MUL2(T, X, X);               // x^2
    ull V; FMA2(V, T, C_B, C_A);        // A + B x^2
    MUL2(V, V, X);                      // z
    float vx, vy; unpack2(V, vx, vy);
    float tx, ty;
    asm("tanh.approx.f32 %0, %1;" : "=f"(tx) : "f"(vx));
    asm("tanh.approx.f32 %0, %1;" : "=f"(ty) : "f"(vy));
    ull TH = pack2(tx, ty);
    ull XH; MUL2(XH, X, C_HALF);        // x/2
    ull O;  FMA2(O, XH, TH, XH);        // 0.5 x (1 + tanh z)
    float ox, oy; unpack2(O, ox, oy);
    return __floats2half2_rn(ox, oy);
}

template<int K, int UNROLL>
__device__ __forceinline__ void sparse_layer_p(
    const __half2* __restrict__ src, __half2* __restrict__ dst,
    const int* __restrict__ idx, const float* __restrict__ w,
    const float* __restrict__ bias, int p, int fo, int warp)
{
    const __half2* srow = src + p * PADH2;
    __half2*       drow = dst + p * PADH2;
    #pragma unroll UNROLL
    for (int pb = warp; pb < NFP; pb += NW) {
        const int f = 2 * pb + fo;
        const float b = __ldg(bias + f);
        float ax = b, ay = b;
        if constexpr (K == 2) {
            int2   j  = __ldg((const int2*)(idx) + f);
            float2 ww = __ldg((const float2*)(w) + f);
            float2 g0 = __half22float2(srow[j.x]);
            float2 g1 = __half22float2(srow[j.y]);
            ax = fmaf(ww.x, g0.x, ax);  ay = fmaf(ww.x, g0.y, ay);
            ax = fmaf(ww.y, g1.x, ax);  ay = fmaf(ww.y, g1.y, ay);
        } else if constexpr (K == 4) {
            int4   j  = __ldg((const int4*)(idx) + f);
            float4 ww = __ldg((const float4*)(w) + f);
            float2 g0 = __half22float2(srow[j.x]);
            float2 g1 = __half22float2(srow[j.y]);
            float2 g2 = __half22float2(srow[j.z]);
            float2 g3 = __half22float2(srow[j.w]);
            float tx = ww.y * g1.x,            ty = ww.y * g1.y;
            ax = fmaf(ww.x, g0.x, ax);         ay = fmaf(ww.x, g0.y, ay);
            tx = fmaf(ww.w, g3.x, tx);         ty = fmaf(ww.w, g3.y, ty);
            ax = fmaf(ww.z, g2.x, ax);         ay = fmaf(ww.z, g2.y, ay);
            ax += tx;                          ay += ty;
        } else {  // K == 8
            int4   ja = __ldg((const int4*)(idx) + 2 * f);
            int4   jb = __ldg((const int4*)(idx) + 2 * f + 1);
            float4 wa = __ldg((const float4*)(w) + 2 * f);
            float4 wb = __ldg((const float4*)(w) + 2 * f + 1);
            float2 g0 = __half22float2(srow[ja.x]);
            float2 g1 = __half22float2(srow[ja.y]);
            float2 g2 = __half22float2(srow[ja.z]);
            float2 g3 = __half22float2(srow[ja.w]);
            float tx = wa.y * g1.x,            ty = wa.y * g1.y;
            ax = fmaf(wa.x, g0.x, ax);         ay = fmaf(wa.x, g0.y, ay);
            tx = fmaf(wa.w, g3.x, tx);         ty = fmaf(wa.w, g3.y, ty);
            ax = fmaf(wa.z, g2.x, ax);         ay = fmaf(wa.z, g2.y, ay);
            float2 g4 = __half22float2(srow[jb.x]);
            float2 g5 = __half22float2(srow[jb.y]);
            float2 g6 = __half22float2(srow[jb.z]);
            float2 g7 = __half22float2(srow[jb.w]);
            tx = fmaf(wb.y, g5.x, tx);         ty = fmaf(wb.y, g5.y, ty);
            ax = fmaf(wb.x, g4.x, ax);         ay = fmaf(wb.x, g4.y, ay);
            tx = fmaf(wb.w, g7.x, tx);         ty = fmaf(wb.w, g7.y, ty);
            ax = fmaf(wb.z, g6.x, ax);         ay = fmaf(wb.z, g6.y, ay);
            ax += tx;                          ay += ty;
        }
        drow[f] = gelu2(ax, ay);
    }
}

extern __shared__ __align__(16) char smem_raw[];

__global__ __launch_bounds__(NT, 2)
void circnn_kernel(const float* __restrict__ x,
                   const int*   __restrict__ idx1, const float* __restrict__ w1, const float* __restrict__ b1,
                   const int*   __restrict__ idx2, const float* __restrict__ w2, const float* __restrict__ b2,
                   const int*   __restrict__ idx3, const float* __restrict__ w3, const float* __restrict__ b3,
                   const float* __restrict__ fc_w, const float* __restrict__ fc_b,
                   float* __restrict__ out, int B)
{
    __half2* bufA = (__half2*)smem_raw;          // NPAIR*PADH2 half2 = 50,304 B
    __half2* bufB = bufA + NPAIR * PADH2;
    float*   part = (float*)smem_raw;            // alias bufA after layer3
    float*   lgts = part + NW * S * NCLS;

    const int tid  = threadIdx.x;
    const int lane = tid & 31;
    const int warp = tid >> 5;
    const int p    = lane & 15;
    const int fo   = lane >> 4;
    const long base = (long)blockIdx.x * S;

    // --- input: warp w owns sample pair w; coalesced row loads, conflict-free STS.64 ---
    {
        const long s0 = base + 2 * warp;
        const float4* r0 = (const float4*)(x + s0 * (long)D);
        const float4* r1 = (const float4*)(x + (s0 + 1) * (long)D);
        uint2* drow = (uint2*)((char*)smem_raw + (warp * PADH2) * 4);
        for (int k = lane; k < D / 4; k += 32) {
            float4 a = __ldg(r0 + k);
            float4 b = __ldg(r1 + k);
            __half2 h0 = __floats2half2_rn(a.x, b.x);
            __half2 h1 = __floats2half2_rn(a.y, b.y);
            __half2 h2 = __floats2half2_rn(a.z, b.z);
            __half2 h3 = __floats2half2_rn(a.w, b.w);
            uint2 v0, v1;
            v0.x = *(unsigned*)&h0;  v0.y = *(unsigned*)&h1;
            v1.x = *(unsigned*)&h2;  v1.y = *(unsigned*)&h3;
            drow[2 * k]     = v0;
            drow[2 * k + 1] = v1;
        }
    }
    __syncthreads();

    sparse_layer_p<2, 4>(bufA, bufB, idx1, w1, b1, p, fo, warp);
    __syncthreads();
    sparse_layer_p<4, 4>(bufB, bufA, idx2, w2, b2, p, fo, warp);
    __syncthreads();
    sparse_layer_p<8, 1>(bufA, bufB, idx3, w3, b3, p, fo, warp);
    __syncthreads();

    // --- FC partials: lane = sample; feature-packed f32x2 FMAs ---
    {
        ull acc2[NCLS];
        #pragma unroll
        for (int c = 0; c < NCLS; ++c) acc2[c] = pack2(0.0f, 0.0f);

        const __half* hB = (const __half*)bufB;
        const int sp = lane >> 1, hi = lane & 1;
        const __half* hrow = hB + sp * (PADH2 * 2) + hi;
        for (int c4 = warp; c4 < D / 4; c4 += NW) {
            const int f = c4 * 4;
            float h0 = __half2float(hrow[(f + 0) * 2]);
            float h1 = __half2float(hrow[(f + 1) * 2]);
            float h2 = __half2float(hrow[(f + 2) * 2]);
            float h3 = __half2float(hrow[(f + 3) * 2]);
            ull H01 = pack2(h0, h1);
            ull H23 = pack2(h2, h3);
            #pragma unroll
            for (int c = 0; c < NCLS; ++c) {
                float4 wv = __ldg((const float4*)(fc_w + c * D) + c4);
                ull W01 = pack2(wv.x, wv.y);
                ull W23 = pack2(wv.z, wv.w);
                FMA2(acc2[c], W01, H01, acc2[c]);
                FMA2(acc2[c], W23, H23, acc2[c]);
            }
        }
        __syncthreads();   // bufA dead for everyone -> alias as part
        float* pp = part + (warp * S + lane) * NCLS;
        #pragma unroll
        for (int c = 0; c < NCLS; ++c) {
            float lo, hv; unpack2(acc2[c], lo, hv);
            pp[c] = lo + hv;
        }
    }
    __syncthreads();

    // --- stage 1 reduction: 320 threads, one (sample, class) each ---
    if (tid < S * NCLS) {
        const int s = tid / NCLS;
        const int c = tid - s * NCLS;
        float sum = __ldg(fc_b + c);
        #pragma unroll
        for (int w = 0; w < NW; ++w)
            sum += part[(w * S + s) * NCLS + c];
        lgts[s * NCLS + c] = sum;
    }
    __syncthreads();

    // --- softmax: thread t handles sample t ---
    if (tid < S) {
        const long gs = base + tid;
        if (gs < B) {
            float l[NCLS];
            #pragma unroll
            for (int c = 0; c < NCLS; ++c) l[c] = lgts[tid * NCLS + c];
            float m = l[0];
            #pragma unroll
            for (int c = 1; c < NCLS; ++c) m = fmaxf(m, l[c]);
            float sum = 0.0f;
            #pragma unroll
            for (int c = 0; c < NCLS; ++c) { l[c] = __expf(l[c] - m); sum += l[c]; }
            const float inv = __fdividef(1.0f, sum);
            float* o = out + gs * NCLS;
            #pragma unroll
            for (int c = 0; c < NCLS; ++c) o[c] = l[c] * inv;
        }
    }
}

extern "C" void kernel_launch(void* const* d_in, const int* in_sizes, int n_in,
                              void* d_out, int out_size)
{
    const float* x    = (const float*)d_in[0];
    const int*   idx1 = (const int*)  d_in[1];
    const float* w1   = (const float*)d_in[2];
    const float* b1   = (const float*)d_in[3];
    const int*   idx2 = (const int*)  d_in[4];
    const float* w2   = (const float*)d_in[5];
    const float* b2   = (const float*)d_in[6];
    const int*   idx3 = (const int*)  d_in[7];
    const float* w3   = (const float*)d_in[8];
    const float* b3   = (const float*)d_in[9];
    const float* fc_w = (const float*)d_in[10];
    const float* fc_b = (const float*)d_in[11];
    float* out = (float*)d_out;

    const int B = in_sizes[0] / D;
    const int grid = (B + S - 1) / S;
    const int smem_bytes = 2 * NPAIR * PADH2 * (int)sizeof(__half2);  // 100,608

    cudaFuncSetAttribute(circnn_kernel,
                         cudaFuncAttributeMaxDynamicSharedMemorySize, smem_bytes);

    circnn_kernel<<<grid, NT, smem_bytes>>>(x, idx1, w1, b1, idx2, w2, b2,
                                            idx3, w3, b3, fc_w, fc_b, out, B);
}

// round 11
// speedup vs baseline: 2.8990x; 1.0963x over previous
#include <cuda_runtime.h>
#include <cuda_fp16.h>

// CircularNN R10: R9 + packed per-feature weight records built by a prep
// kernel into __device__ scratch (idx as u16 byte-offsets, bias folded in),
// and an idx-prefetch software pipeline on the K=8 layer.
// Layout unchanged: sample-pair interleaved fp16 activations, S=32, NT=512,
// 2 CTAs/SM, PADH2=786, MUFU.TANH gelu, f32x2 packed math.

#define D      784
#define PADH2  786
#define S      32
#define NPAIR  16
#define NW     16
#define NT     512
#define NCLS   10
#define NFP    392

typedef unsigned long long ull;

// ---- packed records (filled by prep kernel each launch) ----
// rec1[f]      = {w0, w1, b, bits(i0*4 | i1*4<<16)}
// rec2[f].w    = {w0..w3}; .meta = {bits(i0,i1), bits(i2,i3), b, -}
// rec3a[f]     = taps 0-3 (+bias in meta.z); rec3b[f] = taps 4-7
struct __align__(16) RecT { float4 w; float4 meta; };
__device__ float4 g_rec1[D];
__device__ RecT   g_rec2[D];
__device__ RecT   g_rec3a[D];
__device__ RecT   g_rec3b[D];

__device__ __forceinline__ unsigned fau(float f) { return __float_as_uint(f); }

__global__ void prep_kernel(const int* __restrict__ idx1, const float* __restrict__ w1, const float* __restrict__ b1,
                            const int* __restrict__ idx2, const float* __restrict__ w2, const float* __restrict__ b2,
                            const int* __restrict__ idx3, const float* __restrict__ w3, const float* __restrict__ b3)
{
    int f = blockIdx.x * blockDim.x + threadIdx.x;
    if (f >= D) return;

    // layer 1 (K=2)
    {
        unsigned i0 = (unsigned)idx1[2*f] * 4u, i1 = (unsigned)idx1[2*f+1] * 4u;
        g_rec1[f] = make_float4(w1[2*f], w1[2*f+1], b1[f], __uint_as_float(i0 | (i1 << 16)));
    }
    // layer 2 (K=4)
    {
        unsigned i0 = (unsigned)idx2[4*f]   * 4u, i1 = (unsigned)idx2[4*f+1] * 4u;
        unsigned i2 = (unsigned)idx2[4*f+2] * 4u, i3 = (unsigned)idx2[4*f+3] * 4u;
        RecT r;
        r.w    = make_float4(w2[4*f], w2[4*f+1], w2[4*f+2], w2[4*f+3]);
        r.meta = make_float4(__uint_as_float(i0 | (i1 << 16)),
                             __uint_as_float(i2 | (i3 << 16)), b2[f], 0.0f);
        g_rec2[f] = r;
    }
    // layer 3 (K=8) split into two 32B records
    {
        unsigned i0 = (unsigned)idx3[8*f]   * 4u, i1 = (unsigned)idx3[8*f+1] * 4u;
        unsigned i2 = (unsigned)idx3[8*f+2] * 4u, i3 = (unsigned)idx3[8*f+3] * 4u;
        unsigned i4 = (unsigned)idx3[8*f+4] * 4u, i5 = (unsigned)idx3[8*f+5] * 4u;
        unsigned i6 = (unsigned)idx3[8*f+6] * 4u, i7 = (unsigned)idx3[8*f+7] * 4u;
        RecT ra, rb;
        ra.w    = make_float4(w3[8*f],   w3[8*f+1], w3[8*f+2], w3[8*f+3]);
        ra.meta = make_float4(__uint_as_float(i0 | (i1 << 16)),
                              __uint_as_float(i2 | (i3 << 16)), b3[f], 0.0f);
        rb.w    = make_float4(w3[8*f+4], w3[8*f+5], w3[8*f+6], w3[8*f+7]);
        rb.meta = make_float4(__uint_as_float(i4 | (i5 << 16)),
                              __uint_as_float(i6 | (i7 << 16)), 0.0f, 0.0f);
        g_rec3a[f] = ra;
        g_rec3b[f] = rb;
    }
}

// ---- packed f32x2 helpers ----
__device__ __forceinline__ ull pack2(float a, float b) {
    ull r; asm("mov.b64 %0, {%1, %2};" : "=l"(r) : "f"(a), "f"(b)); return r;
}
__device__ __forceinline__ void unpack2(ull v, float& a, float& b) {
    asm("mov.b64 {%0, %1}, %2;" : "=f"(a), "=f"(b) : "l"(v));
}
#define FMA2(d,a,b,c) asm("fma.rn.f32x2 %0, %1, %2, %3;" : "=l"(d) : "l"(a), "l"(b), "l"(c))
#define MUL2(d,a,b)   asm("mul.rn.f32x2 %0, %1, %2;"     : "=l"(d) : "l"(a), "l"(b))

// tanh-form gelu via MUFU.TANH
__device__ __forceinline__ __half2 gelu2(float ax, float ay) {
    const ull C_A    = pack2(0.7978845608f, 0.7978845608f);
    const ull C_B    = pack2(0.0356774081f, 0.0356774081f);
    const ull C_HALF = pack2(0.5f, 0.5f);
    ull X = pack2(ax, ay);
    ull T; MUL2(T, X, X);
    ull V; FMA2(V, T, C_B, C_A);
    MUL2(V, V, X);
    float vx, vy; unpack2(V, vx, vy);
    float tx, ty;
    asm("tanh.approx.f32 %0, %1;" : "=f"(tx) : "f"(vx));
    asm("tanh.approx.f32 %0, %1;" : "=f"(ty) : "f"(vy));
    ull TH = pack2(tx, ty);
    ull XH; MUL2(XH, X, C_HALF);
    ull O;  FMA2(O, XH, TH, XH);
    float ox, oy; unpack2(O, ox, oy);
    return __floats2half2_rn(ox, oy);
}

__device__ __forceinline__ float2 ghalf(const char* sb, unsigned off) {
    return __half22float2(*(const __half2*)(sb + off));
}

extern __shared__ __align__(16) char smem_raw[];

__global__ __launch_bounds__(NT, 2)
void circnn_kernel(const float* __restrict__ x,
                   const float* __restrict__ fc_w, const float* __restrict__ fc_b,
                   float* __restrict__ out, int B)
{
    __half2* bufA = (__half2*)smem_raw;          // NPAIR*PADH2 half2 = 50,304 B
    __half2* bufB = bufA + NPAIR * PADH2;
    float*   part = (float*)smem_raw;            // alias bufA after layer3
    float*   lgts = part + NW * S * NCLS;

    const int tid  = threadIdx.x;
    const int lane = tid & 31;
    const int warp = tid >> 5;
    const int p    = lane & 15;
    const int fo   = lane >> 4;
    const long base = (long)blockIdx.x * S;

    // --- input: warp w owns sample pair w; coalesced loads, conflict-free STS.64 ---
    {
        const long s0 = base + 2 * warp;
        const float4* r0 = (const float4*)(x + s0 * (long)D);
        const float4* r1 = (const float4*)(x + (s0 + 1) * (long)D);
        uint2* drow = (uint2*)((char*)smem_raw + (warp * PADH2) * 4);
        for (int k = lane; k < D / 4; k += 32) {
            float4 a = __ldg(r0 + k);
            float4 b = __ldg(r1 + k);
            __half2 h0 = __floats2half2_rn(a.x, b.x);
            __half2 h1 = __floats2half2_rn(a.y, b.y);
            __half2 h2 = __floats2half2_rn(a.z, b.z);
            __half2 h3 = __floats2half2_rn(a.w, b.w);
            uint2 v0, v1;
            v0.x = *(unsigned*)&h0;  v0.y = *(unsigned*)&h1;
            v1.x = *(unsigned*)&h2;  v1.y = *(unsigned*)&h3;
            drow[2 * k]     = v0;
            drow[2 * k + 1] = v1;
        }
    }
    __syncthreads();

    // ---- layer 1 (K=2): one 16B record per feature ----
    {
        const char* sb = (const char*)(bufA + p * PADH2);
        __half2*  drow = bufB + p * PADH2;
        #pragma unroll 4
        for (int pb = warp; pb < NFP; pb += NW) {
            const int f = 2 * pb + fo;
            float4 r = __ldg(g_rec1 + f);
            unsigned ii = fau(r.w);
            float2 g0 = ghalf(sb, ii & 0xFFFFu);
            float2 g1 = ghalf(sb, ii >> 16);
            float ax = fmaf(r.x, g0.x, r.z), ay = fmaf(r.x, g0.y, r.z);
            ax = fmaf(r.y, g1.x, ax);        ay = fmaf(r.y, g1.y, ay);
            drow[f] = gelu2(ax, ay);
        }
    }
    __syncthreads();

    // ---- layer 2 (K=4): one 32B record per feature ----
    {
        const char* sb = (const char*)(bufB + p * PADH2);
        __half2*  drow = bufA + p * PADH2;
        #pragma unroll 4
        for (int pb = warp; pb < NFP; pb += NW) {
            const int f = 2 * pb + fo;
            float4 w = __ldg(&g_rec2[f].w);
            float4 m = __ldg(&g_rec2[f].meta);
            unsigned iA = fau(m.x), iB = fau(m.y);
            float2 g0 = ghalf(sb, iA & 0xFFFFu);
            float2 g1 = ghalf(sb, iA >> 16);
            float2 g2 = ghalf(sb, iB & 0xFFFFu);
            float2 g3 = ghalf(sb, iB >> 16);
            float ax = m.z, ay = m.z;
            float tx = w.y * g1.x,        ty = w.y * g1.y;
            ax = fmaf(w.x, g0.x, ax);     ay = fmaf(w.x, g0.y, ay);
            tx = fmaf(w.w, g3.x, tx);     ty = fmaf(w.w, g3.y, ty);
            ax = fmaf(w.z, g2.x, ax);     ay = fmaf(w.z, g2.y, ay);
            ax += tx;                     ay += ty;
            drow[f] = gelu2(ax, ay);
        }
    }
    __syncthreads();

    // ---- layer 3 (K=8): two 32B records, idx-meta prefetch pipeline ----
    {
        const char* sb = (const char*)(bufA + p * PADH2);
        __half2*  drow = bufB + p * PADH2;
        int pb = warp;
        float4 ma = __ldg(&g_rec3a[2 * pb + fo].meta);
        #pragma unroll 1
        for (; pb < NFP; pb += NW) {
            const int f  = 2 * pb + fo;
            const int pn = pb + NW;
            const int fn = (pn < NFP) ? (2 * pn + fo) : f;
            float4 man = __ldg(&g_rec3a[fn].meta);     // prefetch next idx/bias
            float4 mb  = __ldg(&g_rec3b[f].meta);
            float4 wa  = __ldg(&g_rec3a[f].w);
            float4 wb  = __ldg(&g_rec3b[f].w);
            unsigned iA = fau(ma.x), iB = fau(ma.y);
            unsigned iC = fau(mb.x), iD = fau(mb.y);
            float2 g0 = ghalf(sb, iA & 0xFFFFu);
            float2 g1 = ghalf(sb, iA >> 16);
            float2 g2 = ghalf(sb, iB & 0xFFFFu);
            float2 g3 = ghalf(sb, iB >> 16);
            float ax = ma.z, ay = ma.z;
            float tx = wa.y * g1.x,       ty = wa.y * g1.y;
            ax = fmaf(wa.x, g0.x, ax);    ay = fmaf(wa.x, g0.y, ay);
            tx = fmaf(wa.w, g3.x, tx);    ty = fmaf(wa.w, g3.y, ty);
            ax = fmaf(wa.z, g2.x, ax);    ay = fmaf(wa.z, g2.y, ay);
            float2 g4 = ghalf(sb, iC & 0xFFFFu);
            float2 g5 = ghalf(sb, iC >> 16);
            float2 g6 = ghalf(sb, iD & 0xFFFFu);
            float2 g7 = ghalf(sb, iD >> 16);
            tx = fmaf(wb.y, g5.x, tx);    ty = fmaf(wb.y, g5.y, ty);
            ax = fmaf(wb.x, g4.x, ax);    ay = fmaf(wb.x, g4.y, ay);
            tx = fmaf(wb.w, g7.x, tx);    ty = fmaf(wb.w, g7.y, ty);
            ax = fmaf(wb.z, g6.x, ax);    ay = fmaf(wb.z, g6.y, ay);
            ax += tx;                     ay += ty;
            drow[f] = gelu2(ax, ay);
            ma = man;
        }
    }
    __syncthreads();

    // --- FC partials: lane = sample; feature-packed f32x2 FMAs ---
    {
        ull acc2[NCLS];
        #pragma unroll
        for (int c = 0; c < NCLS; ++c) acc2[c] = pack2(0.0f, 0.0f);

        const __half* hB = (const __half*)bufB;
        const int sp = lane >> 1, hi = lane & 1;
        const __half* hrow = hB + sp * (PADH2 * 2) + hi;
        for (int c4 = warp; c4 < D / 4; c4 += NW) {
            const int f = c4 * 4;
            float h0 = __half2float(hrow[(f + 0) * 2]);
            float h1 = __half2float(hrow[(f + 1) * 2]);
            float h2 = __half2float(hrow[(f + 2) * 2]);
            float h3 = __half2float(hrow[(f + 3) * 2]);
            ull H01 = pack2(h0, h1);
            ull H23 = pack2(h2, h3);
            #pragma unroll
            for (int c = 0; c < NCLS; ++c) {
                float4 wv = __ldg((const float4*)(fc_w + c * D) + c4);
                ull W01 = pack2(wv.x, wv.y);
                ull W23 = pack2(wv.z, wv.w);
                FMA2(acc2[c], W01, H01, acc2[c]);
                FMA2(acc2[c], W23, H23, acc2[c]);
            }
        }
        __syncthreads();   // bufA dead for everyone -> alias as part
        float* pp = part + (warp * S + lane) * NCLS;
        #pragma unroll
        for (int c = 0; c < NCLS; ++c) {
            float lo, hv; unpack2(acc2[c], lo, hv);
            pp[c] = lo + hv;
        }
    }
    __syncthreads();

    // --- stage 1 reduction: 320 threads, one (sample, class) each ---
    if (tid < S * NCLS) {
        const int s = tid / NCLS;
        const int c = tid - s * NCLS;
        float sum = __ldg(fc_b + c);
        #pragma unroll
        for (int w = 0; w < NW; ++w)
            sum += part[(w * S + s) * NCLS + c];
        lgts[s * NCLS + c] = sum;
    }
    __syncthreads();

    // --- softmax: thread t handles sample t ---
    if (tid < S) {
        const long gs = base + tid;
        if (gs < B) {
            float l[NCLS];
            #pragma unroll
            for (int c = 0; c < NCLS; ++c) l[c] = lgts[tid * NCLS + c];
            float m = l[0];
            #pragma unroll
            for (int c = 1; c < NCLS; ++c) m = fmaxf(m, l[c]);
            float sum = 0.0f;
            #pragma unroll
            for (int c = 0; c < NCLS; ++c) { l[c] = __expf(l[c] - m); sum += l[c]; }
            const float inv = __fdividef(1.0f, sum);
            float* o = out + gs * NCLS;
            #pragma unroll
            for (int c = 0; c < NCLS; ++c) o[c] = l[c] * inv;
        }
    }
}

extern "C" void kernel_launch(void* const* d_in, const int* in_sizes, int n_in,
                              void* d_out, int out_size)
{
    const float* x    = (const float*)d_in[0];
    const int*   idx1 = (const int*)  d_in[1];
    const float* w1   = (const float*)d_in[2];
    const float* b1   = (const float*)d_in[3];
    const int*   idx2 = (const int*)  d_in[4];
    const float* w2   = (const float*)d_in[5];
    const float* b2   = (const float*)d_in[6];
    const int*   idx3 = (const int*)  d_in[7];
    const float* w3   = (const float*)d_in[8];
    const float* b3   = (const float*)d_in[9];
    const float* fc_w = (const float*)d_in[10];
    const float* fc_b = (const float*)d_in[11];
    float* out = (float*)d_out;

    const int B = in_sizes[0] / D;
    const int grid = (B + S - 1) / S;
    const int smem_bytes = 2 * NPAIR * PADH2 * (int)sizeof(__half2);  // 100,608

    prep_kernel<<<(D + 255) / 256, 256>>>(idx1, w1, b1, idx2, w2, b2, idx3, w3, b3);

    cudaFuncSetAttribute(circnn_kernel,
                         cudaFuncAttributeMaxDynamicSharedMemorySize, smem_bytes);

    circnn_kernel<<<grid, NT, smem_bytes>>>(x, fc_w, fc_b, out, B);
}

// round 12
// speedup vs baseline: 2.9613x; 1.0215x over previous
#include <cuda_runtime.h>
#include <cuda_fp16.h>

// CircularNN R11: R10 + fp16 gather arithmetic. Per tap: 1 LDS.32 (half2
// sample pair) + 1 HFMA2 with a pre-duplicated half2 weight (records built
// by prep kernel; u16 byte-offset indices, bias as dup half2). Accumulated
// half2 converted to fp32 once per feature; gelu stays packed fp32 MUFU.TANH.
// Layout: sample-pair interleaved fp16 activations, S=32, NT=512, 2 CTAs/SM.

#define D      784
#define PADH2  786
#define S      32
#define NPAIR  16
#define NW     16
#define NT     512
#define NCLS   10
#define NFP    392

typedef unsigned long long ull;

// ---- packed records (filled by prep kernel each launch) ----
// g_r1[f]  = {i0|i1<<16, dup(w0), dup(w1), dup(b)}                (K=2)
// g_r2a[f] = {i01, i23, dup(w0), dup(w1)}; g_r2b[f]={dup(w2),dup(w3),dup(b),0}
// g_i3[f]  = {i01,i23,i45,i67}; g_w3a/b = dup(w0..3)/dup(w4..7); g_b3 = dup(b)
__device__ uint4    g_r1[D];
__device__ uint4    g_r2a[D], g_r2b[D];
__device__ uint4    g_i3[D],  g_w3a[D], g_w3b[D];
__device__ unsigned g_b3[D];

__device__ __forceinline__ unsigned duph(float w) {
    unsigned s = __half_as_ushort(__float2half_rn(w));
    return s | (s << 16);
}
__device__ __forceinline__ __half2 u2h(unsigned u) {
    return *reinterpret_cast<const __half2*>(&u);
}

__global__ void prep_kernel(const int* __restrict__ idx1, const float* __restrict__ w1, const float* __restrict__ b1,
                            const int* __restrict__ idx2, const float* __restrict__ w2, const float* __restrict__ b2,
                            const int* __restrict__ idx3, const float* __restrict__ w3, const float* __restrict__ b3)
{
    int f = blockIdx.x * blockDim.x + threadIdx.x;
    if (f >= D) return;

    // layer 1 (K=2)
    {
        unsigned i0 = (unsigned)idx1[2*f] * 4u, i1 = (unsigned)idx1[2*f+1] * 4u;
        uint4 r;
        r.x = i0 | (i1 << 16);
        r.y = duph(w1[2*f]);
        r.z = duph(w1[2*f+1]);
        r.w = duph(b1[f]);
        g_r1[f] = r;
    }
    // layer 2 (K=4)
    {
        unsigned i0 = (unsigned)idx2[4*f]   * 4u, i1 = (unsigned)idx2[4*f+1] * 4u;
        unsigned i2 = (unsigned)idx2[4*f+2] * 4u, i3 = (unsigned)idx2[4*f+3] * 4u;
        uint4 a, b;
        a.x = i0 | (i1 << 16);
        a.y = i2 | (i3 << 16);
        a.z = duph(w2[4*f]);
        a.w = duph(w2[4*f+1]);
        b.x = duph(w2[4*f+2]);
        b.y = duph(w2[4*f+3]);
        b.z = duph(b2[f]);
        b.w = 0;
        g_r2a[f] = a;
        g_r2b[f] = b;
    }
    // layer 3 (K=8)
    {
        unsigned i0 = (unsigned)idx3[8*f]   * 4u, i1 = (unsigned)idx3[8*f+1] * 4u;
        unsigned i2 = (unsigned)idx3[8*f+2] * 4u, i3 = (unsigned)idx3[8*f+3] * 4u;
        unsigned i4 = (unsigned)idx3[8*f+4] * 4u, i5 = (unsigned)idx3[8*f+5] * 4u;
        unsigned i6 = (unsigned)idx3[8*f+6] * 4u, i7 = (unsigned)idx3[8*f+7] * 4u;
        uint4 I, Wa, Wb;
        I.x = i0 | (i1 << 16);  I.y = i2 | (i3 << 16);
        I.z = i4 | (i5 << 16);  I.w = i6 | (i7 << 16);
        Wa.x = duph(w3[8*f]);   Wa.y = duph(w3[8*f+1]);
        Wa.z = duph(w3[8*f+2]); Wa.w = duph(w3[8*f+3]);
        Wb.x = duph(w3[8*f+4]); Wb.y = duph(w3[8*f+5]);
        Wb.z = duph(w3[8*f+6]); Wb.w = duph(w3[8*f+7]);
        g_i3[f] = I;  g_w3a[f] = Wa;  g_w3b[f] = Wb;
        g_b3[f] = duph(b3[f]);
    }
}

// ---- packed f32x2 helpers ----
__device__ __forceinline__ ull pack2(float a, float b) {
    ull r; asm("mov.b64 %0, {%1, %2};" : "=l"(r) : "f"(a), "f"(b)); return r;
}
__device__ __forceinline__ void unpack2(ull v, float& a, float& b) {
    asm("mov.b64 {%0, %1}, %2;" : "=f"(a), "=f"(b) : "l"(v));
}
#define FMA2(d,a,b,c) asm("fma.rn.f32x2 %0, %1, %2, %3;" : "=l"(d) : "l"(a), "l"(b), "l"(c))
#define MUL2(d,a,b)   asm("mul.rn.f32x2 %0, %1, %2;"     : "=l"(d) : "l"(a), "l"(b))

// tanh-form gelu via MUFU.TANH, packed fp32
__device__ __forceinline__ __half2 gelu2(float ax, float ay) {
    const ull C_A    = pack2(0.7978845608f, 0.7978845608f);
    const ull C_B    = pack2(0.0356774081f, 0.0356774081f);
    const ull C_HALF = pack2(0.5f, 0.5f);
    ull X = pack2(ax, ay);
    ull T; MUL2(T, X, X);
    ull V; FMA2(V, T, C_B, C_A);
    MUL2(V, V, X);
    float vx, vy; unpack2(V, vx, vy);
    float tx, ty;
    asm("tanh.approx.f32 %0, %1;" : "=f"(tx) : "f"(vx));
    asm("tanh.approx.f32 %0, %1;" : "=f"(ty) : "f"(vy));
    ull TH = pack2(tx, ty);
    ull XH; MUL2(XH, X, C_HALF);
    ull O;  FMA2(O, XH, TH, XH);
    float ox, oy; unpack2(O, ox, oy);
    return __floats2half2_rn(ox, oy);
}

#define LH2(off) (*(const __half2*)(sb + (off)))

extern __shared__ __align__(16) char smem_raw[];

__global__ __launch_bounds__(NT, 2)
void circnn_kernel(const float* __restrict__ x,
                   const float* __restrict__ fc_w, const float* __restrict__ fc_b,
                   float* __restrict__ out, int B)
{
    __half2* bufA = (__half2*)smem_raw;          // NPAIR*PADH2 half2 = 50,304 B
    __half2* bufB = bufA + NPAIR * PADH2;
    float*   part = (float*)smem_raw;            // alias bufA after layer3
    float*   lgts = part + NW * S * NCLS;

    const int tid  = threadIdx.x;
    const int lane = tid & 31;
    const int warp = tid >> 5;
    const int p    = lane & 15;
    const int fo   = lane >> 4;
    const long base = (long)blockIdx.x * S;

    // --- input: warp w owns sample pair w; coalesced loads, conflict-free STS.64 ---
    {
        const long s0 = base + 2 * warp;
        const float4* r0 = (const float4*)(x + s0 * (long)D);
        const float4* r1 = (const float4*)(x + (s0 + 1) * (long)D);
        uint2* drow = (uint2*)((char*)smem_raw + (warp * PADH2) * 4);
        for (int k = lane; k < D / 4; k += 32) {
            float4 a = __ldg(r0 + k);
            float4 b = __ldg(r1 + k);
            __half2 h0 = __floats2half2_rn(a.x, b.x);
            __half2 h1 = __floats2half2_rn(a.y, b.y);
            __half2 h2 = __floats2half2_rn(a.z, b.z);
            __half2 h3 = __floats2half2_rn(a.w, b.w);
            uint2 v0, v1;
            v0.x = *(unsigned*)&h0;  v0.y = *(unsigned*)&h1;
            v1.x = *(unsigned*)&h2;  v1.y = *(unsigned*)&h3;
            drow[2 * k]     = v0;
            drow[2 * k + 1] = v1;
        }
    }
    __syncthreads();

    // ---- layer 1 (K=2): one 16B record; 2 LDS + 2 HFMA2 per feature ----
    {
        const char* sb = (const char*)(bufA + p * PADH2);
        __half2*  drow = bufB + p * PADH2;
        #pragma unroll 4
        for (int pb = warp; pb < NFP; pb += NW) {
            const int f = 2 * pb + fo;
            uint4 r = __ldg(g_r1 + f);
            __half2 acc = u2h(r.w);
            acc = __hfma2(u2h(r.y), LH2(r.x & 0xFFFFu), acc);
            acc = __hfma2(u2h(r.z), LH2(r.x >> 16), acc);
            float2 a = __half22float2(acc);
            drow[f] = gelu2(a.x, a.y);
        }
    }
    __syncthreads();

    // ---- layer 2 (K=4): two 16B records; two HFMA2 trees ----
    {
        const char* sb = (const char*)(bufB + p * PADH2);
        __half2*  drow = bufA + p * PADH2;
        #pragma unroll 4
        for (int pb = warp; pb < NFP; pb += NW) {
            const int f = 2 * pb + fo;
            uint4 A  = __ldg(&g_r2a[f]);
            uint4 Bv = __ldg(&g_r2b[f]);
            __half2 acc = u2h(Bv.z);
            __half2 t   = __hmul2(u2h(A.w),  LH2(A.x >> 16));
            acc = __hfma2(u2h(A.z),  LH2(A.x & 0xFFFFu), acc);
            t   = __hfma2(u2h(Bv.y), LH2(A.y >> 16), t);
            acc = __hfma2(u2h(Bv.x), LH2(A.y & 0xFFFFu), acc);
            acc = __hadd2(acc, t);
            float2 a = __half22float2(acc);
            drow[f] = gelu2(a.x, a.y);
        }
    }
    __syncthreads();

    // ---- layer 3 (K=8): idx prefetch pipeline; two HFMA2 trees ----
    {
        const char* sb = (const char*)(bufA + p * PADH2);
        __half2*  drow = bufB + p * PADH2;
        int pb = warp;
        uint4 I = __ldg(&g_i3[2 * pb + fo]);
        #pragma unroll 1
        for (; pb < NFP; pb += NW) {
            const int f  = 2 * pb + fo;
            const int pn = pb + NW;
            const int fn = (pn < NFP) ? (2 * pn + fo) : f;
            uint4 In = __ldg(&g_i3[fn]);           // prefetch next indices
            uint4 Wa = __ldg(&g_w3a[f]);
            uint4 Wb = __ldg(&g_w3b[f]);
            __half2 acc = u2h(__ldg(&g_b3[f]));
            __half2 t   = __hmul2(u2h(Wa.y), LH2(I.x >> 16));
            acc = __hfma2(u2h(Wa.x), LH2(I.x & 0xFFFFu), acc);
            t   = __hfma2(u2h(Wa.w), LH2(I.y >> 16), t);
            acc = __hfma2(u2h(Wa.z), LH2(I.y & 0xFFFFu), acc);
            t   = __hfma2(u2h(Wb.y), LH2(I.z >> 16), t);
            acc = __hfma2(u2h(Wb.x), LH2(I.z & 0xFFFFu), acc);
            t   = __hfma2(u2h(Wb.w), LH2(I.w >> 16), t);
            acc = __hfma2(u2h(Wb.z), LH2(I.w & 0xFFFFu), acc);
            acc = __hadd2(acc, t);
            float2 a = __half22float2(acc);
            drow[f] = gelu2(a.x, a.y);
            I = In;
        }
    }
    __syncthreads();

    // --- FC partials: lane = sample; feature-packed f32x2 FMAs ---
    {
        ull acc2[NCLS];
        #pragma unroll
        for (int c = 0; c < NCLS; ++c) acc2[c] = pack2(0.0f, 0.0f);

        const __half* hB = (const __half*)bufB;
        const int sp = lane >> 1, hi = lane & 1;
        const __half* hrow = hB + sp * (PADH2 * 2) + hi;
        for (int c4 = warp; c4 < D / 4; c4 += NW) {
            const int f = c4 * 4;
            float h0 = __half2float(hrow[(f + 0) * 2]);
            float h1 = __half2float(hrow[(f + 1) * 2]);
            float h2 = __half2float(hrow[(f + 2) * 2]);
            float h3 = __half2float(hrow[(f + 3) * 2]);
            ull H01 = pack2(h0, h1);
            ull H23 = pack2(h2, h3);
            #pragma unroll
            for (int c = 0; c < NCLS; ++c) {
                float4 wv = __ldg((const float4*)(fc_w + c * D) + c4);
                ull W01 = pack2(wv.x, wv.y);
                ull W23 = pack2(wv.z, wv.w);
                FMA2(acc2[c], W01, H01, acc2[c]);
                FMA2(acc2[c], W23, H23, acc2[c]);
            }
        }
        __syncthreads();   // bufA dead for everyone -> alias as part
        float* pp = part + (warp * S + lane) * NCLS;
        #pragma unroll
        for (int c = 0; c < NCLS; ++c) {
            float lo, hv; unpack2(acc2[c], lo, hv);
            pp[c] = lo + hv;
        }
    }
    __syncthreads();

    // --- stage 1 reduction: 320 threads, one (sample, class) each ---
    if (tid < S * NCLS) {
        const int s = tid / NCLS;
        const int c = tid - s * NCLS;
        float sum = __ldg(fc_b + c);
        #pragma unroll
        for (int w = 0; w < NW; ++w)
            sum += part[(w * S + s) * NCLS + c];
        lgts[s * NCLS + c] = sum;
    }
    __syncthreads();

    // --- softmax: thread t handles sample t ---
    if (tid < S) {
        const long gs = base + tid;
        if (gs < B) {
            float l[NCLS];
            #pragma unroll
            for (int c = 0; c < NCLS; ++c) l[c] = lgts[tid * NCLS + c];
            float m = l[0];
            #pragma unroll
            for (int c = 1; c < NCLS; ++c) m = fmaxf(m, l[c]);
            float sum = 0.0f;
            #pragma unroll
            for (int c = 0; c < NCLS; ++c) { l[c] = __expf(l[c] - m); sum += l[c]; }
            const float inv = __fdividef(1.0f, sum);
            float* o = out + gs * NCLS;
            #pragma unroll
            for (int c = 0; c < NCLS; ++c) o[c] = l[c] * inv;
        }
    }
}

extern "C" void kernel_launch(void* const* d_in, const int* in_sizes, int n_in,
                              void* d_out, int out_size)
{
    const float* x    = (const float*)d_in[0];
    const int*   idx1 = (const int*)  d_in[1];
    const float* w1   = (const float*)d_in[2];
    const float* b1   = (const float*)d_in[3];
    const int*   idx2 = (const int*)  d_in[4];
    const float* w2   = (const float*)d_in[5];
    const float* b2   = (const float*)d_in[6];
    const int*   idx3 = (const int*)  d_in[7];
    const float* w3   = (const float*)d_in[8];
    const float* b3   = (const float*)d_in[9];
    const float* fc_w = (const float*)d_in[10];
    const float* fc_b = (const float*)d_in[11];
    float* out = (float*)d_out;

    const int B = in_sizes[0] / D;
    const int grid = (B + S - 1) / S;
    const int smem_bytes = 2 * NPAIR * PADH2 * (int)sizeof(__half2);  // 100,608

    prep_kernel<<<(D + 255) / 256, 256>>>(idx1, w1, b1, idx2, w2, b2, idx3, w3, b3);

    cudaFuncSetAttribute(circnn_kernel,
                         cudaFuncAttributeMaxDynamicSharedMemorySize, smem_bytes);

    circnn_kernel<<<grid, NT, smem_bytes>>>(x, fc_w, fc_b, out, B);
}